// round 1
// baseline (speedup 1.0000x reference)
#include <cuda_runtime.h>
#include <cstdint>

#define BATCH 4
#define NNODE 20000
#define DN 64
#define DM 128
#define NE 160000
#define NL 2
#define ROWS (BATCH*NNODE)   // 80000

// ---------------- scratch (device globals; no allocations allowed) ----------
__device__ float g_H[(size_t)ROWS * DM];          // 41 MB
__device__ float g_P[(size_t)ROWS * 3 * DM];      // 123 MB
__device__ float g_E0[(size_t)NE * DM];           // 82 MB
__device__ float g_E1[(size_t)NE * DM];           // 82 MB
__device__ float g_agg[(size_t)ROWS * DM];        // 41 MB

// ---------------- fp32 SGEMM: C[M x 128] = A[M x K] @ W[K x 128] + bias -----
// C element (m, n) stored at C[m*ldc + coff + n].  128x128 block tile,
// 8x8 per thread, 256 threads, BK=8.
__global__ __launch_bounds__(256)
void sgemm128(const float* __restrict__ A, const float* __restrict__ W,
              const float* __restrict__ bias, float* __restrict__ C,
              int M, int K, int ldc, int coff)
{
    __shared__ float As[8][128];
    __shared__ float Bs[8][128];
    const int bm  = blockIdx.x * 128;
    const int tid = threadIdx.x;
    const int tx  = tid & 15;   // column group (cols tx*8 .. tx*8+7)
    const int ty  = tid >> 4;   // row group    (rows ty*8 .. ty*8+7)

    float acc[8][8];
#pragma unroll
    for (int i = 0; i < 8; i++)
#pragma unroll
        for (int j = 0; j < 8; j++) acc[i][j] = 0.f;

    for (int k0 = 0; k0 < K; k0 += 8) {
        // A tile: 128 rows x 8 ks, via float4 (256 threads x 1 float4)
        {
            int m  = tid >> 1;
            int kq = (tid & 1) * 4;
            int gm = bm + m;
            float4 v = make_float4(0.f, 0.f, 0.f, 0.f);
            if (gm < M)
                v = *reinterpret_cast<const float4*>(A + (size_t)gm * K + k0 + kq);
            As[kq + 0][m] = v.x; As[kq + 1][m] = v.y;
            As[kq + 2][m] = v.z; As[kq + 3][m] = v.w;
        }
        // W tile: 8 ks x 128 cols, via float4
        {
            int kk = tid >> 5;
            int nq = (tid & 31) * 4;
            float4 v = *reinterpret_cast<const float4*>(W + (size_t)(k0 + kk) * 128 + nq);
            *reinterpret_cast<float4*>(&Bs[kk][nq]) = v;
        }
        __syncthreads();
#pragma unroll
        for (int kk = 0; kk < 8; kk++) {
            float a[8], b[8];
#pragma unroll
            for (int i = 0; i < 8; i++) a[i] = As[kk][ty * 8 + i];
#pragma unroll
            for (int j = 0; j < 8; j++) b[j] = Bs[kk][tx * 8 + j];
#pragma unroll
            for (int i = 0; i < 8; i++)
#pragma unroll
                for (int j = 0; j < 8; j++)
                    acc[i][j] = fmaf(a[i], b[j], acc[i][j]);
        }
        __syncthreads();
    }
#pragma unroll
    for (int i = 0; i < 8; i++) {
        int gm = bm + ty * 8 + i;
        if (gm < M) {
#pragma unroll
            for (int j = 0; j < 8; j += 4) {
                int n = tx * 8 + j;
                float4 o;
                o.x = acc[i][j + 0] + bias[n + 0];
                o.y = acc[i][j + 1] + bias[n + 1];
                o.z = acc[i][j + 2] + bias[n + 2];
                o.w = acc[i][j + 3] + bias[n + 3];
                *reinterpret_cast<float4*>(C + (size_t)gm * ldc + coff + n) = o;
            }
        }
    }
}

// ---------------- zero agg ---------------------------------------------------
__global__ void zero_kernel(float4* __restrict__ p, int n4)
{
    int i = blockIdx.x * blockDim.x + threadIdx.x;
    if (i < n4) p[i] = make_float4(0.f, 0.f, 0.f, 0.f);
}

// ---------------- scatter: one warp per (relation, edge) --------------------
// agg[b, dst] += P[b, src, r] (+ Eterm_r[e])   for b in 0..3
__global__ __launch_bounds__(256)
void scatter_kernel(const float* __restrict__ P,
                    const float* __restrict__ E0,
                    const float* __restrict__ E1,
                    const int* __restrict__ ei0,
                    const int* __restrict__ ei1,
                    const int* __restrict__ ei2,
                    float* __restrict__ agg)
{
    int gw   = (blockIdx.x * blockDim.x + threadIdx.x) >> 5;
    int lane = threadIdx.x & 31;
    if (gw >= 3 * NE) return;
    int r = gw / NE;
    int e = gw - r * NE;

    const int* ei = (r == 0) ? ei0 : (r == 1) ? ei1 : ei2;
    int src = ei[e];
    int dst = ei[NE + e];

    float4 et = make_float4(0.f, 0.f, 0.f, 0.f);
    if (r == 0)      et = reinterpret_cast<const float4*>(E0)[(size_t)e * 32 + lane];
    else if (r == 1) et = reinterpret_cast<const float4*>(E1)[(size_t)e * 32 + lane];

#pragma unroll
    for (int b = 0; b < BATCH; b++) {
        const float4 p = *reinterpret_cast<const float4*>(
            P + ((size_t)(b * NNODE + src) * 384 + r * 128) + lane * 4);
        float4 v = make_float4(p.x + et.x, p.y + et.y, p.z + et.z, p.w + et.w);
        float* d = agg + ((size_t)(b * NNODE + dst) * 128) + lane * 4;
        asm volatile("red.global.add.v4.f32 [%0], {%1,%2,%3,%4};"
                     :: "l"(d), "f"(v.x), "f"(v.y), "f"(v.z), "f"(v.w)
                     : "memory");
    }
}

// ---------------- fused add + relu + LayerNorm (warp per row) ---------------
__global__ __launch_bounds__(256)
void addrelu_ln_kernel(const float* __restrict__ H,
                       const float* __restrict__ agg,
                       const float* __restrict__ gamma,
                       const float* __restrict__ beta,
                       float* __restrict__ out)
{
    int gw   = (blockIdx.x * blockDim.x + threadIdx.x) >> 5;
    int lane = threadIdx.x & 31;
    if (gw >= ROWS) return;

    const float4 h = reinterpret_cast<const float4*>(H)[(size_t)gw * 32 + lane];
    const float4 a = reinterpret_cast<const float4*>(agg)[(size_t)gw * 32 + lane];
    float x0 = h.x + fmaxf(a.x, 0.f);
    float x1 = h.y + fmaxf(a.y, 0.f);
    float x2 = h.z + fmaxf(a.z, 0.f);
    float x3 = h.w + fmaxf(a.w, 0.f);

    float s = x0 + x1 + x2 + x3;
#pragma unroll
    for (int off = 16; off > 0; off >>= 1)
        s += __shfl_xor_sync(0xffffffffu, s, off);
    float mu = s * (1.f / 128.f);

    float d0 = x0 - mu, d1 = x1 - mu, d2 = x2 - mu, d3 = x3 - mu;
    float q = d0 * d0 + d1 * d1 + d2 * d2 + d3 * d3;
#pragma unroll
    for (int off = 16; off > 0; off >>= 1)
        q += __shfl_xor_sync(0xffffffffu, q, off);
    float rstd = rsqrtf(q * (1.f / 128.f) + 1e-5f);

    float4 gg = reinterpret_cast<const float4*>(gamma)[lane];
    float4 bb = reinterpret_cast<const float4*>(beta)[lane];
    float4 o;
    o.x = d0 * rstd * gg.x + bb.x;
    o.y = d1 * rstd * gg.y + bb.y;
    o.z = d2 * rstd * gg.z + bb.z;
    o.w = d3 * rstd * gg.w + bb.w;
    reinterpret_cast<float4*>(out)[(size_t)gw * 32 + lane] = o;
}

// ---------------- launch -----------------------------------------------------
extern "C" void kernel_launch(void* const* d_in, const int* in_sizes, int n_in,
                              void* d_out, int out_size)
{
    const float* node_feat = (const float*)d_in[0];   // [4,20000,64]
    const float* in_W      = (const float*)d_in[1];   // [64,128]
    const float* in_b      = (const float*)d_in[2];   // [128]
    const float* node_W    = (const float*)d_in[3];   // [2,3,128,128]
    const float* node_b    = (const float*)d_in[4];   // [2,3,128]
    const float* edge_W    = (const float*)d_in[5];   // [2,2,16,128]
    const float* edge_b    = (const float*)d_in[6];   // [2,2,128]
    const float* ln_g      = (const float*)d_in[7];   // [2,128]
    const float* ln_b      = (const float*)d_in[8];   // [2,128]
    const float* ea0       = (const float*)d_in[9];   // [160000,16]
    const float* ea1       = (const float*)d_in[10];  // [160000,16]
    const int*   ei0       = (const int*)d_in[11];    // [2,160000]
    const int*   ei1       = (const int*)d_in[12];
    const int*   ei2       = (const int*)d_in[13];
    float* out = (float*)d_out;

    float *H, *P, *E0p, *E1p, *agg;
    cudaGetSymbolAddress((void**)&H,   g_H);
    cudaGetSymbolAddress((void**)&P,   g_P);
    cudaGetSymbolAddress((void**)&E0p, g_E0);
    cudaGetSymbolAddress((void**)&E1p, g_E1);
    cudaGetSymbolAddress((void**)&agg, g_agg);

    // input projection: [80000,64] @ [64,128]
    sgemm128<<<(ROWS + 127) / 128, 256>>>(node_feat, in_W, in_b, H, ROWS, DN, DM, 0);

    for (int l = 0; l < NL; l++) {
        // per-relation node GEMMs -> P[:, r*128:(r+1)*128]
        for (int r = 0; r < 3; r++) {
            sgemm128<<<(ROWS + 127) / 128, 256>>>(
                H,
                node_W + (size_t)(l * 3 + r) * DM * DM,
                node_b + (size_t)(l * 3 + r) * DM,
                P, ROWS, DM, 3 * DM, r * DM);
        }
        // edge-attr GEMMs (relations 0 and 1)
        sgemm128<<<(NE + 127) / 128, 256>>>(
            ea0, edge_W + (size_t)(l * 2 + 0) * 16 * DM,
            edge_b + (size_t)(l * 2 + 0) * DM, E0p, NE, 16, DM, 0);
        sgemm128<<<(NE + 127) / 128, 256>>>(
            ea1, edge_W + (size_t)(l * 2 + 1) * 16 * DM,
            edge_b + (size_t)(l * 2 + 1) * DM, E1p, NE, 16, DM, 0);

        // zero agg
        zero_kernel<<<(ROWS * 32 + 255) / 256, 256>>>((float4*)agg, ROWS * 32);

        // scatter-add messages (warp per (relation, edge), 4 batches inside)
        {
            long long threads = 3LL * NE * 32;
            int blocks = (int)((threads + 255) / 256);
            scatter_kernel<<<blocks, 256>>>(P, E0p, E1p, ei0, ei1, ei2, agg);
        }

        // H = LN(H + relu(agg)); final layer writes d_out
        float* dst = (l == NL - 1) ? out : H;
        addrelu_ln_kernel<<<(ROWS * 32 + 255) / 256, 256>>>(
            H, agg, ln_g + (size_t)l * DM, ln_b + (size_t)l * DM, dst);
    }
}

// round 2
// speedup vs baseline: 1.0568x; 1.0568x over previous
#include <cuda_runtime.h>
#include <cstdint>

#define BATCH 4
#define NNODE 20000
#define DN 64
#define DM 128
#define NE 160000
#define NL 2
#define ROWS (BATCH*NNODE)   // 80000
#define NEDGE_TOT (3*NE)     // 480000

// ---------------- scratch (device globals) ----------------------------------
__device__ float g_H[(size_t)ROWS * DM];          // 41 MB
__device__ float g_P[(size_t)ROWS * 3 * DM];      // 123 MB
__device__ float g_E0[(size_t)NE * DM];           // 82 MB
__device__ float g_E1[(size_t)NE * DM];           // 82 MB
__device__ int   g_deg[NNODE];
__device__ int   g_off[NNODE + 1];
__device__ int   g_cursor[NNODE];
__device__ int2  g_entries[NEDGE_TOT];

// ---------------- fp32 SGEMM, double-buffered -------------------------------
// C[m, coff+n] (ldc) = A[M x K] @ W[K x 128] + bias. 128x128 tile, 8x8/thread.
__global__ __launch_bounds__(256)
void sgemm128(const float* __restrict__ A, const float* __restrict__ W,
              const float* __restrict__ bias, float* __restrict__ C,
              int M, int K, int ldc, int coff)
{
    __shared__ float As[2][8][128];
    __shared__ float Bs[2][8][128];
    const int bm  = blockIdx.x * 128;
    const int tid = threadIdx.x;
    const int tx  = tid & 15;
    const int ty  = tid >> 4;

    float acc[8][8];
#pragma unroll
    for (int i = 0; i < 8; i++)
#pragma unroll
        for (int j = 0; j < 8; j++) acc[i][j] = 0.f;

    const int lm  = tid >> 1;          // A staging: row within tile
    const int lk4 = (tid & 1) * 4;     // A staging: k offset
    const int lkB = tid >> 5;          // B staging: k row
    const int lnB = (tid & 31) * 4;    // B staging: col
    const bool arow_ok = (bm + lm) < M;
    const float* Aptr = A + (size_t)(bm + lm) * K + lk4;

    float4 av = make_float4(0.f, 0.f, 0.f, 0.f);
    if (arow_ok) av = *reinterpret_cast<const float4*>(Aptr);
    float4 bv = *reinterpret_cast<const float4*>(W + (size_t)lkB * 128 + lnB);
    As[0][lk4 + 0][lm] = av.x; As[0][lk4 + 1][lm] = av.y;
    As[0][lk4 + 2][lm] = av.z; As[0][lk4 + 3][lm] = av.w;
    *reinterpret_cast<float4*>(&Bs[0][lkB][lnB]) = bv;
    __syncthreads();

    int cur = 0;
    for (int k0 = 8; k0 < K; k0 += 8) {
        // prefetch next tile from gmem
        av = make_float4(0.f, 0.f, 0.f, 0.f);
        if (arow_ok) av = *reinterpret_cast<const float4*>(Aptr + k0);
        bv = *reinterpret_cast<const float4*>(W + (size_t)(k0 + lkB) * 128 + lnB);
        // compute current tile
#pragma unroll
        for (int kk = 0; kk < 8; kk++) {
            float a[8], b[8];
#pragma unroll
            for (int i = 0; i < 8; i++) a[i] = As[cur][kk][ty * 8 + i];
#pragma unroll
            for (int j = 0; j < 8; j++) b[j] = Bs[cur][kk][tx * 8 + j];
#pragma unroll
            for (int i = 0; i < 8; i++)
#pragma unroll
                for (int j = 0; j < 8; j++)
                    acc[i][j] = fmaf(a[i], b[j], acc[i][j]);
        }
        int nxt = cur ^ 1;
        As[nxt][lk4 + 0][lm] = av.x; As[nxt][lk4 + 1][lm] = av.y;
        As[nxt][lk4 + 2][lm] = av.z; As[nxt][lk4 + 3][lm] = av.w;
        *reinterpret_cast<float4*>(&Bs[nxt][lkB][lnB]) = bv;
        __syncthreads();
        cur = nxt;
    }
#pragma unroll
    for (int kk = 0; kk < 8; kk++) {
        float a[8], b[8];
#pragma unroll
        for (int i = 0; i < 8; i++) a[i] = As[cur][kk][ty * 8 + i];
#pragma unroll
        for (int j = 0; j < 8; j++) b[j] = Bs[cur][kk][tx * 8 + j];
#pragma unroll
        for (int i = 0; i < 8; i++)
#pragma unroll
            for (int j = 0; j < 8; j++)
                acc[i][j] = fmaf(a[i], b[j], acc[i][j]);
    }

#pragma unroll
    for (int i = 0; i < 8; i++) {
        int gm = bm + ty * 8 + i;
        if (gm < M) {
#pragma unroll
            for (int j = 0; j < 8; j += 4) {
                int n = tx * 8 + j;
                float4 o;
                o.x = acc[i][j + 0] + bias[n + 0];
                o.y = acc[i][j + 1] + bias[n + 1];
                o.z = acc[i][j + 2] + bias[n + 2];
                o.w = acc[i][j + 3] + bias[n + 3];
                *reinterpret_cast<float4*>(C + (size_t)gm * ldc + coff + n) = o;
            }
        }
    }
}

// ---------------- CSR build (runs once per launch) --------------------------
__global__ void zero_deg_kernel(int* __restrict__ deg)
{
    int i = blockIdx.x * blockDim.x + threadIdx.x;
    if (i < NNODE) deg[i] = 0;
}

__global__ void hist_kernel(const int* __restrict__ ei0,
                            const int* __restrict__ ei1,
                            const int* __restrict__ ei2,
                            int* __restrict__ deg)
{
    int i = blockIdx.x * blockDim.x + threadIdx.x;
    if (i >= NEDGE_TOT) return;
    int r = i / NE, e = i - r * NE;
    const int* ei = (r == 0) ? ei0 : (r == 1) ? ei1 : ei2;
    atomicAdd(deg + ei[NE + e], 1);
}

// single-block exclusive scan over deg -> off, cursor
__global__ __launch_bounds__(256)
void scan_kernel(const int* __restrict__ deg, int* __restrict__ off,
                 int* __restrict__ cursor)
{
    __shared__ int warp_sums[8];
    __shared__ int s_carry;
    const int tid  = threadIdx.x;
    const int lane = tid & 31;
    const int wid  = tid >> 5;
    if (tid == 0) s_carry = 0;
    __syncthreads();

    for (int base = 0; base < NNODE; base += 256) {
        int i = base + tid;
        int x = (i < NNODE) ? deg[i] : 0;
        int v = x;
#pragma unroll
        for (int d = 1; d < 32; d <<= 1) {
            int t = __shfl_up_sync(0xffffffffu, v, d);
            if (lane >= d) v += t;
        }
        if (lane == 31) warp_sums[wid] = v;
        __syncthreads();
        if (wid == 0 && lane < 8) {
            int s = warp_sums[lane];
#pragma unroll
            for (int d = 1; d < 8; d <<= 1) {
                int t = __shfl_up_sync(0x000000ffu, s, d);
                if (lane >= d) s += t;
            }
            warp_sums[lane] = s;
        }
        __syncthreads();
        int add  = (wid > 0) ? warp_sums[wid - 1] : 0;
        int incl = v + add + s_carry;
        if (i < NNODE) {
            off[i]    = incl - x;
            cursor[i] = incl - x;
        }
        __syncthreads();
        if (tid == 255) s_carry = incl;
        __syncthreads();
    }
    if (tid == 0) off[NNODE] = s_carry;
}

__global__ void fill_kernel(const int* __restrict__ ei0,
                            const int* __restrict__ ei1,
                            const int* __restrict__ ei2,
                            int* __restrict__ cursor,
                            int2* __restrict__ entries)
{
    int i = blockIdx.x * blockDim.x + threadIdx.x;
    if (i >= NEDGE_TOT) return;
    int r = i / NE, e = i - r * NE;
    const int* ei = (r == 0) ? ei0 : (r == 1) ? ei1 : ei2;
    int src = ei[e];
    int dst = ei[NE + e];
    int pos = atomicAdd(cursor + dst, 1);
    entries[pos] = make_int2(src, (r << 20) | e);
}

// ---------------- gather + residual + relu + LayerNorm ----------------------
// one warp per node; all 4 batches accumulated in registers
__global__ __launch_bounds__(256)
void gather_ln_kernel(const float* __restrict__ P,
                      const float* __restrict__ E0,
                      const float* __restrict__ E1,
                      const float* __restrict__ H,
                      const int* __restrict__ off,
                      const int2* __restrict__ entries,
                      const float* __restrict__ gamma,
                      const float* __restrict__ beta,
                      float* __restrict__ out)
{
    int warp = (blockIdx.x * blockDim.x + threadIdx.x) >> 5;
    int lane = threadIdx.x & 31;
    if (warp >= NNODE) return;
    const int node = warp;
    const int jb = off[node];
    const int je = off[node + 1];

    float4 acc[BATCH];
#pragma unroll
    for (int b = 0; b < BATCH; b++) acc[b] = make_float4(0.f, 0.f, 0.f, 0.f);

    for (int j = jb; j < je; j++) {
        int2 m  = entries[j];
        int src = m.x;
        int rel = m.y >> 20;
        int e   = m.y & 0xFFFFF;

        float4 et = make_float4(0.f, 0.f, 0.f, 0.f);
        if (rel == 0)      et = reinterpret_cast<const float4*>(E0)[(size_t)e * 32 + lane];
        else if (rel == 1) et = reinterpret_cast<const float4*>(E1)[(size_t)e * 32 + lane];

        const float* pb = P + (size_t)src * 384 + rel * 128 + lane * 4;
#pragma unroll
        for (int b = 0; b < BATCH; b++) {
            float4 p = *reinterpret_cast<const float4*>(pb + (size_t)b * NNODE * 384);
            acc[b].x += p.x + et.x;
            acc[b].y += p.y + et.y;
            acc[b].z += p.z + et.z;
            acc[b].w += p.w + et.w;
        }
    }

    float4 gg = reinterpret_cast<const float4*>(gamma)[lane];
    float4 bb = reinterpret_cast<const float4*>(beta)[lane];

#pragma unroll
    for (int b = 0; b < BATCH; b++) {
        size_t row = (size_t)(b * NNODE + node);
        float4 h = reinterpret_cast<const float4*>(H)[row * 32 + lane];
        float x0 = h.x + fmaxf(acc[b].x, 0.f);
        float x1 = h.y + fmaxf(acc[b].y, 0.f);
        float x2 = h.z + fmaxf(acc[b].z, 0.f);
        float x3 = h.w + fmaxf(acc[b].w, 0.f);

        float s = x0 + x1 + x2 + x3;
#pragma unroll
        for (int o = 16; o > 0; o >>= 1) s += __shfl_xor_sync(0xffffffffu, s, o);
        float mu = s * (1.f / 128.f);

        float d0 = x0 - mu, d1 = x1 - mu, d2 = x2 - mu, d3 = x3 - mu;
        float q = d0 * d0 + d1 * d1 + d2 * d2 + d3 * d3;
#pragma unroll
        for (int o = 16; o > 0; o >>= 1) q += __shfl_xor_sync(0xffffffffu, q, o);
        float rstd = rsqrtf(q * (1.f / 128.f) + 1e-5f);

        float4 ov;
        ov.x = d0 * rstd * gg.x + bb.x;
        ov.y = d1 * rstd * gg.y + bb.y;
        ov.z = d2 * rstd * gg.z + bb.z;
        ov.w = d3 * rstd * gg.w + bb.w;
        reinterpret_cast<float4*>(out)[row * 32 + lane] = ov;
    }
}

// ---------------- launch -----------------------------------------------------
extern "C" void kernel_launch(void* const* d_in, const int* in_sizes, int n_in,
                              void* d_out, int out_size)
{
    const float* node_feat = (const float*)d_in[0];
    const float* in_W      = (const float*)d_in[1];
    const float* in_b      = (const float*)d_in[2];
    const float* node_W    = (const float*)d_in[3];
    const float* node_b    = (const float*)d_in[4];
    const float* edge_W    = (const float*)d_in[5];
    const float* edge_b    = (const float*)d_in[6];
    const float* ln_g      = (const float*)d_in[7];
    const float* ln_b      = (const float*)d_in[8];
    const float* ea0       = (const float*)d_in[9];
    const float* ea1       = (const float*)d_in[10];
    const int*   ei0       = (const int*)d_in[11];
    const int*   ei1       = (const int*)d_in[12];
    const int*   ei2       = (const int*)d_in[13];
    float* out = (float*)d_out;

    float *H, *P, *E0p, *E1p;
    int *deg, *off, *cursor;
    int2* entries;
    cudaGetSymbolAddress((void**)&H,       g_H);
    cudaGetSymbolAddress((void**)&P,       g_P);
    cudaGetSymbolAddress((void**)&E0p,     g_E0);
    cudaGetSymbolAddress((void**)&E1p,     g_E1);
    cudaGetSymbolAddress((void**)&deg,     g_deg);
    cudaGetSymbolAddress((void**)&off,     g_off);
    cudaGetSymbolAddress((void**)&cursor,  g_cursor);
    cudaGetSymbolAddress((void**)&entries, g_entries);

    // CSR build (edge indices are launch inputs; rebuilt every replay)
    zero_deg_kernel<<<(NNODE + 255) / 256, 256>>>(deg);
    hist_kernel<<<(NEDGE_TOT + 255) / 256, 256>>>(ei0, ei1, ei2, deg);
    scan_kernel<<<1, 256>>>(deg, off, cursor);
    fill_kernel<<<(NEDGE_TOT + 255) / 256, 256>>>(ei0, ei1, ei2, cursor, entries);

    // input projection
    sgemm128<<<(ROWS + 127) / 128, 256>>>(node_feat, in_W, in_b, H, ROWS, DN, DM, 0);

    for (int l = 0; l < NL; l++) {
        for (int r = 0; r < 3; r++) {
            sgemm128<<<(ROWS + 127) / 128, 256>>>(
                H, node_W + (size_t)(l * 3 + r) * DM * DM,
                node_b + (size_t)(l * 3 + r) * DM,
                P, ROWS, DM, 3 * DM, r * DM);
        }
        sgemm128<<<(NE + 127) / 128, 256>>>(
            ea0, edge_W + (size_t)(l * 2 + 0) * 16 * DM,
            edge_b + (size_t)(l * 2 + 0) * DM, E0p, NE, 16, DM, 0);
        sgemm128<<<(NE + 127) / 128, 256>>>(
            ea1, edge_W + (size_t)(l * 2 + 1) * 16 * DM,
            edge_b + (size_t)(l * 2 + 1) * DM, E1p, NE, 16, DM, 0);

        float* dst = (l == NL - 1) ? out : H;
        gather_ln_kernel<<<(NNODE * 32 + 255) / 256, 256>>>(
            P, E0p, E1p, H, off, entries,
            ln_g + (size_t)l * DM, ln_b + (size_t)l * DM, dst);
    }
}

// round 3
// speedup vs baseline: 1.3060x; 1.2359x over previous
#include <cuda_runtime.h>
#include <cstdint>

#define BATCH 4
#define NNODE 20000
#define DN 64
#define DM 128
#define NE 160000
#define NL 2
#define ROWS (BATCH*NNODE)   // 80000
#define NEDGE_TOT (3*NE)     // 480000

// ---------------- scratch (device globals) ----------------------------------
__device__ float g_H[(size_t)ROWS * DM];            // 41 MB
__device__ float g_G[(size_t)ROWS * 3 * DM];        // 123 MB (gathered H sums)
__device__ float g_Cterm[(size_t)NL * NNODE * DM];  // 20.5 MB
__device__ float g_S0[(size_t)NNODE * 16];
__device__ float g_S1[(size_t)NNODE * 16];
__device__ float g_cnt[(size_t)NNODE * 4];
__device__ int   g_deg[NNODE];
__device__ int   g_off[NNODE + 1];
__device__ int   g_cursor[NNODE];
__device__ int2  g_entries[NEDGE_TOT];

// ---------------- fp32 SGEMM, double-buffered (generic, used for inproj) ----
__global__ __launch_bounds__(256)
void sgemm128(const float* __restrict__ A, const float* __restrict__ W,
              const float* __restrict__ bias, float* __restrict__ C,
              int M, int K, int ldc, int coff)
{
    __shared__ float As[2][8][128];
    __shared__ float Bs[2][8][128];
    const int bm  = blockIdx.x * 128;
    const int tid = threadIdx.x;
    const int tx  = tid & 15;
    const int ty  = tid >> 4;

    float acc[8][8];
#pragma unroll
    for (int i = 0; i < 8; i++)
#pragma unroll
        for (int j = 0; j < 8; j++) acc[i][j] = 0.f;

    const int lm  = tid >> 1;
    const int lk4 = (tid & 1) * 4;
    const int lkB = tid >> 5;
    const int lnB = (tid & 31) * 4;
    const bool arow_ok = (bm + lm) < M;
    const float* Aptr = A + (size_t)(bm + lm) * K + lk4;

    float4 av = make_float4(0.f, 0.f, 0.f, 0.f);
    if (arow_ok) av = *reinterpret_cast<const float4*>(Aptr);
    float4 bv = *reinterpret_cast<const float4*>(W + (size_t)lkB * 128 + lnB);
    As[0][lk4 + 0][lm] = av.x; As[0][lk4 + 1][lm] = av.y;
    As[0][lk4 + 2][lm] = av.z; As[0][lk4 + 3][lm] = av.w;
    *reinterpret_cast<float4*>(&Bs[0][lkB][lnB]) = bv;
    __syncthreads();

    int cur = 0;
    for (int k0 = 8; k0 < K; k0 += 8) {
        av = make_float4(0.f, 0.f, 0.f, 0.f);
        if (arow_ok) av = *reinterpret_cast<const float4*>(Aptr + k0);
        bv = *reinterpret_cast<const float4*>(W + (size_t)(k0 + lkB) * 128 + lnB);
#pragma unroll
        for (int kk = 0; kk < 8; kk++) {
            float a[8], b[8];
#pragma unroll
            for (int i = 0; i < 8; i++) a[i] = As[cur][kk][ty * 8 + i];
#pragma unroll
            for (int j = 0; j < 8; j++) b[j] = Bs[cur][kk][tx * 8 + j];
#pragma unroll
            for (int i = 0; i < 8; i++)
#pragma unroll
                for (int j = 0; j < 8; j++)
                    acc[i][j] = fmaf(a[i], b[j], acc[i][j]);
        }
        int nxt = cur ^ 1;
        As[nxt][lk4 + 0][lm] = av.x; As[nxt][lk4 + 1][lm] = av.y;
        As[nxt][lk4 + 2][lm] = av.z; As[nxt][lk4 + 3][lm] = av.w;
        *reinterpret_cast<float4*>(&Bs[nxt][lkB][lnB]) = bv;
        __syncthreads();
        cur = nxt;
    }
#pragma unroll
    for (int kk = 0; kk < 8; kk++) {
        float a[8], b[8];
#pragma unroll
        for (int i = 0; i < 8; i++) a[i] = As[cur][kk][ty * 8 + i];
#pragma unroll
        for (int j = 0; j < 8; j++) b[j] = Bs[cur][kk][tx * 8 + j];
#pragma unroll
        for (int i = 0; i < 8; i++)
#pragma unroll
            for (int j = 0; j < 8; j++)
                acc[i][j] = fmaf(a[i], b[j], acc[i][j]);
    }
#pragma unroll
    for (int i = 0; i < 8; i++) {
        int gm = bm + ty * 8 + i;
        if (gm < M) {
#pragma unroll
            for (int j = 0; j < 8; j += 4) {
                int n = tx * 8 + j;
                float4 o;
                o.x = acc[i][j + 0] + bias[n + 0];
                o.y = acc[i][j + 1] + bias[n + 1];
                o.z = acc[i][j + 2] + bias[n + 2];
                o.w = acc[i][j + 3] + bias[n + 3];
                *reinterpret_cast<float4*>(C + (size_t)gm * ldc + coff + n) = o;
            }
        }
    }
}

// ---------------- fused GEMM (K=384) + Cterm + residual + relu + LayerNorm --
// out[row] = LN( H[row] + relu( G[row,0:384] @ W[384x128] + Cterm[row%NNODE] ) )
__global__ __launch_bounds__(256)
void gemm_ln_kernel(const float* __restrict__ G, const float* __restrict__ W,
                    const float* __restrict__ H, const float* __restrict__ Ct,
                    const float* __restrict__ gamma, const float* __restrict__ beta,
                    float* __restrict__ out)
{
    __shared__ float As[2][8][128];
    __shared__ float Bs[2][8][128];
    const int bm  = blockIdx.x * 128;
    const int tid = threadIdx.x;
    const int tx  = tid & 15;
    const int ty  = tid >> 4;

    float acc[8][8];
#pragma unroll
    for (int i = 0; i < 8; i++)
#pragma unroll
        for (int j = 0; j < 8; j++) acc[i][j] = 0.f;

    const int lm  = tid >> 1;
    const int lk4 = (tid & 1) * 4;
    const int lkB = tid >> 5;
    const int lnB = (tid & 31) * 4;
    const float* Aptr = G + (size_t)(bm + lm) * 384 + lk4;

    float4 av = *reinterpret_cast<const float4*>(Aptr);
    float4 bv = *reinterpret_cast<const float4*>(W + (size_t)lkB * 128 + lnB);
    As[0][lk4 + 0][lm] = av.x; As[0][lk4 + 1][lm] = av.y;
    As[0][lk4 + 2][lm] = av.z; As[0][lk4 + 3][lm] = av.w;
    *reinterpret_cast<float4*>(&Bs[0][lkB][lnB]) = bv;
    __syncthreads();

    int cur = 0;
#pragma unroll 1
    for (int k0 = 8; k0 < 384; k0 += 8) {
        av = *reinterpret_cast<const float4*>(Aptr + k0);
        bv = *reinterpret_cast<const float4*>(W + (size_t)(k0 + lkB) * 128 + lnB);
#pragma unroll
        for (int kk = 0; kk < 8; kk++) {
            float a[8], b[8];
#pragma unroll
            for (int i = 0; i < 8; i++) a[i] = As[cur][kk][ty * 8 + i];
#pragma unroll
            for (int j = 0; j < 8; j++) b[j] = Bs[cur][kk][tx * 8 + j];
#pragma unroll
            for (int i = 0; i < 8; i++)
#pragma unroll
                for (int j = 0; j < 8; j++)
                    acc[i][j] = fmaf(a[i], b[j], acc[i][j]);
        }
        int nxt = cur ^ 1;
        As[nxt][lk4 + 0][lm] = av.x; As[nxt][lk4 + 1][lm] = av.y;
        As[nxt][lk4 + 2][lm] = av.z; As[nxt][lk4 + 3][lm] = av.w;
        *reinterpret_cast<float4*>(&Bs[nxt][lkB][lnB]) = bv;
        __syncthreads();
        cur = nxt;
    }
#pragma unroll
    for (int kk = 0; kk < 8; kk++) {
        float a[8], b[8];
#pragma unroll
        for (int i = 0; i < 8; i++) a[i] = As[cur][kk][ty * 8 + i];
#pragma unroll
        for (int j = 0; j < 8; j++) b[j] = Bs[cur][kk][tx * 8 + j];
#pragma unroll
        for (int i = 0; i < 8; i++)
#pragma unroll
            for (int j = 0; j < 8; j++)
                acc[i][j] = fmaf(a[i], b[j], acc[i][j]);
    }

    // ---- epilogue: +Cterm, relu, +H, LayerNorm over the 128 cols -----------
    const int nc = tx * 8;
    float4 g0 = *reinterpret_cast<const float4*>(gamma + nc);
    float4 g1 = *reinterpret_cast<const float4*>(gamma + nc + 4);
    float4 b0 = *reinterpret_cast<const float4*>(beta + nc);
    float4 b1 = *reinterpret_cast<const float4*>(beta + nc + 4);
    float gg[8] = {g0.x, g0.y, g0.z, g0.w, g1.x, g1.y, g1.z, g1.w};
    float bb[8] = {b0.x, b0.y, b0.z, b0.w, b1.x, b1.y, b1.z, b1.w};

#pragma unroll
    for (int i = 0; i < 8; i++) {
        const int gm   = bm + ty * 8 + i;
        const int node = gm % NNODE;
        float4 c0 = *reinterpret_cast<const float4*>(Ct + (size_t)node * 128 + nc);
        float4 c1 = *reinterpret_cast<const float4*>(Ct + (size_t)node * 128 + nc + 4);
        float4 h0 = *reinterpret_cast<const float4*>(H + (size_t)gm * 128 + nc);
        float4 h1 = *reinterpret_cast<const float4*>(H + (size_t)gm * 128 + nc + 4);
        float ct[8] = {c0.x, c0.y, c0.z, c0.w, c1.x, c1.y, c1.z, c1.w};
        float hh[8] = {h0.x, h0.y, h0.z, h0.w, h1.x, h1.y, h1.z, h1.w};

        float x[8], s = 0.f;
#pragma unroll
        for (int j = 0; j < 8; j++) {
            x[j] = hh[j] + fmaxf(acc[i][j] + ct[j], 0.f);
            s += x[j];
        }
#pragma unroll
        for (int o = 8; o > 0; o >>= 1) s += __shfl_xor_sync(0xffffffffu, s, o);
        float mu = s * (1.f / 128.f);

        float q = 0.f, d[8];
#pragma unroll
        for (int j = 0; j < 8; j++) { d[j] = x[j] - mu; q += d[j] * d[j]; }
#pragma unroll
        for (int o = 8; o > 0; o >>= 1) q += __shfl_xor_sync(0xffffffffu, q, o);
        float rstd = rsqrtf(q * (1.f / 128.f) + 1e-5f);

        float4 o0, o1;
        o0.x = d[0] * rstd * gg[0] + bb[0]; o0.y = d[1] * rstd * gg[1] + bb[1];
        o0.z = d[2] * rstd * gg[2] + bb[2]; o0.w = d[3] * rstd * gg[3] + bb[3];
        o1.x = d[4] * rstd * gg[4] + bb[4]; o1.y = d[5] * rstd * gg[5] + bb[5];
        o1.z = d[6] * rstd * gg[6] + bb[6]; o1.w = d[7] * rstd * gg[7] + bb[7];
        *reinterpret_cast<float4*>(out + (size_t)gm * 128 + nc)     = o0;
        *reinterpret_cast<float4*>(out + (size_t)gm * 128 + nc + 4) = o1;
    }
}

// ---------------- CSR build --------------------------------------------------
__global__ void zero_deg_kernel(int* __restrict__ deg)
{
    int i = blockIdx.x * blockDim.x + threadIdx.x;
    if (i < NNODE) deg[i] = 0;
}

__global__ void hist_kernel(const int* __restrict__ ei0,
                            const int* __restrict__ ei1,
                            const int* __restrict__ ei2,
                            int* __restrict__ deg)
{
    int i = blockIdx.x * blockDim.x + threadIdx.x;
    if (i >= NEDGE_TOT) return;
    int r = i / NE, e = i - r * NE;
    const int* ei = (r == 0) ? ei0 : (r == 1) ? ei1 : ei2;
    atomicAdd(deg + ei[NE + e], 1);
}

__global__ __launch_bounds__(256)
void scan_kernel(const int* __restrict__ deg, int* __restrict__ off,
                 int* __restrict__ cursor)
{
    __shared__ int warp_sums[8];
    __shared__ int s_carry;
    const int tid  = threadIdx.x;
    const int lane = tid & 31;
    const int wid  = tid >> 5;
    if (tid == 0) s_carry = 0;
    __syncthreads();

    for (int base = 0; base < NNODE; base += 256) {
        int i = base + tid;
        int x = (i < NNODE) ? deg[i] : 0;
        int v = x;
#pragma unroll
        for (int d = 1; d < 32; d <<= 1) {
            int t = __shfl_up_sync(0xffffffffu, v, d);
            if (lane >= d) v += t;
        }
        if (lane == 31) warp_sums[wid] = v;
        __syncthreads();
        if (wid == 0 && lane < 8) {
            int s = warp_sums[lane];
#pragma unroll
            for (int d = 1; d < 8; d <<= 1) {
                int t = __shfl_up_sync(0x000000ffu, s, d);
                if (lane >= d) s += t;
            }
            warp_sums[lane] = s;
        }
        __syncthreads();
        int add  = (wid > 0) ? warp_sums[wid - 1] : 0;
        int incl = v + add + s_carry;
        if (i < NNODE) { off[i] = incl - x; cursor[i] = incl - x; }
        __syncthreads();
        if (tid == 255) s_carry = incl;
        __syncthreads();
    }
    if (tid == 0) off[NNODE] = s_carry;
}

__global__ void fill_kernel(const int* __restrict__ ei0,
                            const int* __restrict__ ei1,
                            const int* __restrict__ ei2,
                            int* __restrict__ cursor,
                            int2* __restrict__ entries)
{
    int i = blockIdx.x * blockDim.x + threadIdx.x;
    if (i >= NEDGE_TOT) return;
    int r = i / NE, e = i - r * NE;
    const int* ei = (r == 0) ? ei0 : (r == 1) ? ei1 : ei2;
    int src = ei[e];
    int dst = ei[NE + e];
    int pos = atomicAdd(cursor + dst, 1);
    entries[pos] = make_int2(src, (r << 20) | e);
}

// ---------------- per-node stats: counts + edge-attr sums -------------------
__global__ __launch_bounds__(256)
void stats_kernel(const int* __restrict__ off, const int2* __restrict__ entries,
                  const float* __restrict__ ea0, const float* __restrict__ ea1,
                  float* __restrict__ S0, float* __restrict__ S1,
                  float* __restrict__ cnt)
{
    int warp = (blockIdx.x * blockDim.x + threadIdx.x) >> 5;
    int lane = threadIdx.x & 31;
    if (warp >= NNODE) return;
    const int jb = off[warp], je = off[warp + 1];
    float s0 = 0.f, s1 = 0.f;
    int c0 = 0, c1 = 0, c2 = 0;
    for (int j = jb; j < je; j++) {
        int2 m = entries[j];
        int rel = m.y >> 20, e = m.y & 0xFFFFF;
        if (rel == 0)      { c0++; if (lane < 16) s0 += ea0[(size_t)e * 16 + lane]; }
        else if (rel == 1) { c1++; if (lane < 16) s1 += ea1[(size_t)e * 16 + lane]; }
        else               { c2++; }
    }
    if (lane < 16) {
        S0[(size_t)warp * 16 + lane] = s0;
        S1[(size_t)warp * 16 + lane] = s1;
    }
    if (lane == 0) {
        cnt[(size_t)warp * 4 + 0] = (float)c0;
        cnt[(size_t)warp * 4 + 1] = (float)c1;
        cnt[(size_t)warp * 4 + 2] = (float)c2;
    }
}

// ---------------- Cterm: per-node, per-layer constant term ------------------
#define CT_NODES 16
__global__ __launch_bounds__(128)
void cterm_kernel(const float* __restrict__ S0, const float* __restrict__ S1,
                  const float* __restrict__ cnt,
                  const float* __restrict__ node_b, const float* __restrict__ edge_W,
                  const float* __restrict__ edge_b, float* __restrict__ Ct)
{
    const int l   = blockIdx.y;
    const int j   = threadIdx.x;
    __shared__ float eW0[16 * 128];
    __shared__ float eW1[16 * 128];
    __shared__ float nb0[128], nb1[128], nb2[128], eb0[128], eb1[128];
    __shared__ float sS[2][32];

    for (int k = 0; k < 16; k++) {
        eW0[k * 128 + j] = edge_W[((size_t)(l * 2 + 0) * 16 + k) * 128 + j];
        eW1[k * 128 + j] = edge_W[((size_t)(l * 2 + 1) * 16 + k) * 128 + j];
    }
    nb0[j] = node_b[(size_t)(l * 3 + 0) * 128 + j];
    nb1[j] = node_b[(size_t)(l * 3 + 1) * 128 + j];
    nb2[j] = node_b[(size_t)(l * 3 + 2) * 128 + j];
    eb0[j] = edge_b[(size_t)(l * 2 + 0) * 128 + j];
    eb1[j] = edge_b[(size_t)(l * 2 + 1) * 128 + j];
    __syncthreads();

    const int nbase = blockIdx.x * CT_NODES;
    for (int t = 0; t < CT_NODES; t++) {
        int node = nbase + t;
        int buf = t & 1;
        if (j < 16)                 sS[buf][j]      = S0[(size_t)node * 16 + j];
        else if (j < 32)            sS[buf][j]      = S1[(size_t)node * 16 + (j - 16)];
        __syncthreads();
        float c0 = cnt[(size_t)node * 4 + 0];
        float c1 = cnt[(size_t)node * 4 + 1];
        float c2 = cnt[(size_t)node * 4 + 2];
        float v = c0 * (nb0[j] + eb0[j]) + c1 * (nb1[j] + eb1[j]) + c2 * nb2[j];
#pragma unroll
        for (int k = 0; k < 16; k++) v = fmaf(sS[buf][k], eW0[k * 128 + j], v);
#pragma unroll
        for (int k = 0; k < 16; k++) v = fmaf(sS[buf][k + 16], eW1[k * 128 + j], v);
        Ct[((size_t)l * NNODE + node) * 128 + j] = v;
        __syncthreads();
    }
}

// ---------------- gather: G_r[b,node] = sum over r-edges of H[b,src] --------
__global__ __launch_bounds__(256)
void gather_kernel(const float* __restrict__ H, const int* __restrict__ off,
                   const int2* __restrict__ entries, float* __restrict__ G)
{
    int warp = (blockIdx.x * blockDim.x + threadIdx.x) >> 5;
    int lane = threadIdx.x & 31;
    if (warp >= NNODE) return;
    const int node = warp;
    const int jb = off[node], je = off[node + 1];

    float4 a0[BATCH], a1[BATCH], a2[BATCH];
#pragma unroll
    for (int b = 0; b < BATCH; b++) {
        a0[b] = make_float4(0.f, 0.f, 0.f, 0.f);
        a1[b] = make_float4(0.f, 0.f, 0.f, 0.f);
        a2[b] = make_float4(0.f, 0.f, 0.f, 0.f);
    }

    for (int j = jb; j < je; j++) {
        int2 m = entries[j];
        int src = m.x;
        int rel = m.y >> 20;
        const float* hb = H + (size_t)src * 128 + lane * 4;
        float4 h[BATCH];
#pragma unroll
        for (int b = 0; b < BATCH; b++)
            h[b] = *reinterpret_cast<const float4*>(hb + (size_t)b * NNODE * 128);
        if (rel == 0) {
#pragma unroll
            for (int b = 0; b < BATCH; b++) {
                a0[b].x += h[b].x; a0[b].y += h[b].y; a0[b].z += h[b].z; a0[b].w += h[b].w;
            }
        } else if (rel == 1) {
#pragma unroll
            for (int b = 0; b < BATCH; b++) {
                a1[b].x += h[b].x; a1[b].y += h[b].y; a1[b].z += h[b].z; a1[b].w += h[b].w;
            }
        } else {
#pragma unroll
            for (int b = 0; b < BATCH; b++) {
                a2[b].x += h[b].x; a2[b].y += h[b].y; a2[b].z += h[b].z; a2[b].w += h[b].w;
            }
        }
    }

#pragma unroll
    for (int b = 0; b < BATCH; b++) {
        float* gb = G + (size_t)(b * NNODE + node) * 384 + lane * 4;
        *reinterpret_cast<float4*>(gb)       = a0[b];
        *reinterpret_cast<float4*>(gb + 128) = a1[b];
        *reinterpret_cast<float4*>(gb + 256) = a2[b];
    }
}

// ---------------- launch -----------------------------------------------------
extern "C" void kernel_launch(void* const* d_in, const int* in_sizes, int n_in,
                              void* d_out, int out_size)
{
    const float* node_feat = (const float*)d_in[0];
    const float* in_W      = (const float*)d_in[1];
    const float* in_b      = (const float*)d_in[2];
    const float* node_W    = (const float*)d_in[3];
    const float* node_b    = (const float*)d_in[4];
    const float* edge_W    = (const float*)d_in[5];
    const float* edge_b    = (const float*)d_in[6];
    const float* ln_g      = (const float*)d_in[7];
    const float* ln_b      = (const float*)d_in[8];
    const float* ea0       = (const float*)d_in[9];
    const float* ea1       = (const float*)d_in[10];
    const int*   ei0       = (const int*)d_in[11];
    const int*   ei1       = (const int*)d_in[12];
    const int*   ei2       = (const int*)d_in[13];
    float* out = (float*)d_out;

    float *H, *G, *Ct, *S0, *S1, *cnt;
    int *deg, *off, *cursor;
    int2* entries;
    cudaGetSymbolAddress((void**)&H,       g_H);
    cudaGetSymbolAddress((void**)&G,       g_G);
    cudaGetSymbolAddress((void**)&Ct,      g_Cterm);
    cudaGetSymbolAddress((void**)&S0,      g_S0);
    cudaGetSymbolAddress((void**)&S1,      g_S1);
    cudaGetSymbolAddress((void**)&cnt,     g_cnt);
    cudaGetSymbolAddress((void**)&deg,     g_deg);
    cudaGetSymbolAddress((void**)&off,     g_off);
    cudaGetSymbolAddress((void**)&cursor,  g_cursor);
    cudaGetSymbolAddress((void**)&entries, g_entries);

    // CSR + per-node stats + per-layer constant terms
    zero_deg_kernel<<<(NNODE + 255) / 256, 256>>>(deg);
    hist_kernel<<<(NEDGE_TOT + 255) / 256, 256>>>(ei0, ei1, ei2, deg);
    scan_kernel<<<1, 256>>>(deg, off, cursor);
    fill_kernel<<<(NEDGE_TOT + 255) / 256, 256>>>(ei0, ei1, ei2, cursor, entries);
    stats_kernel<<<(NNODE * 32 + 255) / 256, 256>>>(off, entries, ea0, ea1, S0, S1, cnt);
    {
        dim3 grid(NNODE / CT_NODES, NL);
        cterm_kernel<<<grid, 128>>>(S0, S1, cnt, node_b, edge_W, edge_b, Ct);
    }

    // input projection
    sgemm128<<<(ROWS + 127) / 128, 256>>>(node_feat, in_W, in_b, H, ROWS, DN, DM, 0);

    for (int l = 0; l < NL; l++) {
        gather_kernel<<<(NNODE * 32 + 255) / 256, 256>>>(H, off, entries, G);
        float* dst = (l == NL - 1) ? out : H;
        gemm_ln_kernel<<<ROWS / 128, 256>>>(
            G, node_W + (size_t)l * 3 * DM * DM, H, Ct + (size_t)l * NNODE * DM,
            ln_g + (size_t)l * DM, ln_b + (size_t)l * DM, dst);
    }
}

// round 4
// speedup vs baseline: 1.7348x; 1.3283x over previous
#include <cuda_runtime.h>
#include <cstdint>

#define BATCH 4
#define NNODE 20000
#define DN 64
#define DM 128
#define NE 160000
#define NL 2
#define ROWS (BATCH*NNODE)   // 80000
#define NEDGE_TOT (3*NE)     // 480000

// ---------------- scratch (device globals) ----------------------------------
__device__ float g_H[(size_t)ROWS * DM];            // 41 MB
__device__ float g_G[(size_t)ROWS * 3 * DM];        // 123 MB (gathered H sums)
__device__ float g_Cterm[(size_t)NL * NNODE * DM];  // 20.5 MB
__device__ float g_S0[(size_t)NNODE * 16];
__device__ float g_S1[(size_t)NNODE * 16];
__device__ float g_cnt[(size_t)NNODE * 4];
__device__ int   g_deg[NNODE];
__device__ int   g_off[NNODE + 1];
__device__ int   g_cursor[NNODE];
__device__ int2  g_entries[NEDGE_TOT];

__device__ __forceinline__ float to_tf32(float x) {
    uint32_t u;
    asm("cvt.rna.tf32.f32 %0, %1;" : "=r"(u) : "f"(x));
    return __uint_as_float(u);
}

// ---------------- fp32 SGEMM (inproj only, K=64) -----------------------------
__global__ __launch_bounds__(256)
void sgemm128(const float* __restrict__ A, const float* __restrict__ W,
              const float* __restrict__ bias, float* __restrict__ C,
              int M, int K, int ldc, int coff)
{
    __shared__ float As[2][8][128];
    __shared__ float Bs[2][8][128];
    const int bm  = blockIdx.x * 128;
    const int tid = threadIdx.x;
    const int tx  = tid & 15;
    const int ty  = tid >> 4;

    float acc[8][8];
#pragma unroll
    for (int i = 0; i < 8; i++)
#pragma unroll
        for (int j = 0; j < 8; j++) acc[i][j] = 0.f;

    const int lm  = tid >> 1;
    const int lk4 = (tid & 1) * 4;
    const int lkB = tid >> 5;
    const int lnB = (tid & 31) * 4;
    const bool arow_ok = (bm + lm) < M;
    const float* Aptr = A + (size_t)(bm + lm) * K + lk4;

    float4 av = make_float4(0.f, 0.f, 0.f, 0.f);
    if (arow_ok) av = *reinterpret_cast<const float4*>(Aptr);
    float4 bv = *reinterpret_cast<const float4*>(W + (size_t)lkB * 128 + lnB);
    As[0][lk4 + 0][lm] = av.x; As[0][lk4 + 1][lm] = av.y;
    As[0][lk4 + 2][lm] = av.z; As[0][lk4 + 3][lm] = av.w;
    *reinterpret_cast<float4*>(&Bs[0][lkB][lnB]) = bv;
    __syncthreads();

    int cur = 0;
    for (int k0 = 8; k0 < K; k0 += 8) {
        av = make_float4(0.f, 0.f, 0.f, 0.f);
        if (arow_ok) av = *reinterpret_cast<const float4*>(Aptr + k0);
        bv = *reinterpret_cast<const float4*>(W + (size_t)(k0 + lkB) * 128 + lnB);
#pragma unroll
        for (int kk = 0; kk < 8; kk++) {
            float a[8], b[8];
#pragma unroll
            for (int i = 0; i < 8; i++) a[i] = As[cur][kk][ty * 8 + i];
#pragma unroll
            for (int j = 0; j < 8; j++) b[j] = Bs[cur][kk][tx * 8 + j];
#pragma unroll
            for (int i = 0; i < 8; i++)
#pragma unroll
                for (int j = 0; j < 8; j++)
                    acc[i][j] = fmaf(a[i], b[j], acc[i][j]);
        }
        int nxt = cur ^ 1;
        As[nxt][lk4 + 0][lm] = av.x; As[nxt][lk4 + 1][lm] = av.y;
        As[nxt][lk4 + 2][lm] = av.z; As[nxt][lk4 + 3][lm] = av.w;
        *reinterpret_cast<float4*>(&Bs[nxt][lkB][lnB]) = bv;
        __syncthreads();
        cur = nxt;
    }
#pragma unroll
    for (int kk = 0; kk < 8; kk++) {
        float a[8], b[8];
#pragma unroll
        for (int i = 0; i < 8; i++) a[i] = As[cur][kk][ty * 8 + i];
#pragma unroll
        for (int j = 0; j < 8; j++) b[j] = Bs[cur][kk][tx * 8 + j];
#pragma unroll
        for (int i = 0; i < 8; i++)
#pragma unroll
            for (int j = 0; j < 8; j++)
                acc[i][j] = fmaf(a[i], b[j], acc[i][j]);
    }
#pragma unroll
    for (int i = 0; i < 8; i++) {
        int gm = bm + ty * 8 + i;
        if (gm < M) {
#pragma unroll
            for (int j = 0; j < 8; j += 4) {
                int n = tx * 8 + j;
                float4 o;
                o.x = acc[i][j + 0] + bias[n + 0];
                o.y = acc[i][j + 1] + bias[n + 1];
                o.z = acc[i][j + 2] + bias[n + 2];
                o.w = acc[i][j + 3] + bias[n + 3];
                *reinterpret_cast<float4*>(C + (size_t)gm * ldc + coff + n) = o;
            }
        }
    }
}

// ---------------- tf32 tensor-core fused GEMM + Cterm + relu + H + LN -------
// out[row] = LN( H[row] + relu( G[row,0:384] @ W[384x128] + Ct[row%NNODE] ) )
// 128x128 tile per CTA, K=384, mma.sync.m16n8k8.tf32, 8 warps (16 rows each).
__global__ __launch_bounds__(256)
void gemm_ln_tf32(const float* __restrict__ G, const float* __restrict__ W,
                  const float* __restrict__ H, const float* __restrict__ Ct,
                  const float* __restrict__ gamma, const float* __restrict__ beta,
                  float* __restrict__ out)
{
    __shared__ union SmemU {
        struct { float A[2][128][20]; float2 B[2][2][128][5]; } mm; // 20480+20480
        float C[64][132];                                           // 33792
    } sm;

    const int tid  = threadIdx.x;
    const int bm   = blockIdx.x * 128;
    const int w    = tid >> 5;
    const int lane = tid & 31;
    const int ly   = lane >> 2;
    const int lx   = lane & 3;

    // staging indices
    const int ar  = tid >> 2;          // A row (and ar+64)
    const int ac  = (tid & 3) * 4;     // A col base
    const int bks = tid >> 7;          // B k-step (0/1)
    const int bkl = (tid >> 5) & 3;    // B k-low (0..3)
    const int bn8 = (tid & 31) * 4;    // B n base

    const float* Aptr0 = G + (size_t)(bm + ar) * 384 + ac;
    const float* Aptr1 = Aptr0 + (size_t)64 * 384;

    float acc[16][4];
#pragma unroll
    for (int nt = 0; nt < 16; nt++)
#pragma unroll
        for (int j = 0; j < 4; j++) acc[nt][j] = 0.f;

    // prologue: stage chunk 0
    {
        float4 va0 = *reinterpret_cast<const float4*>(Aptr0);
        float4 va1 = *reinterpret_cast<const float4*>(Aptr1);
        const float* wr = W + (size_t)(bks * 8 + bkl) * 128 + bn8;
        float4 lo = *reinterpret_cast<const float4*>(wr);
        float4 hi = *reinterpret_cast<const float4*>(wr + 512);
        sm.mm.A[0][ar][ac + 0] = to_tf32(va0.x);
        sm.mm.A[0][ar][ac + 1] = to_tf32(va0.y);
        sm.mm.A[0][ar][ac + 2] = to_tf32(va0.z);
        sm.mm.A[0][ar][ac + 3] = to_tf32(va0.w);
        sm.mm.A[0][ar + 64][ac + 0] = to_tf32(va1.x);
        sm.mm.A[0][ar + 64][ac + 1] = to_tf32(va1.y);
        sm.mm.A[0][ar + 64][ac + 2] = to_tf32(va1.z);
        sm.mm.A[0][ar + 64][ac + 3] = to_tf32(va1.w);
        sm.mm.B[0][bks][bn8 + 0][bkl] = make_float2(to_tf32(lo.x), to_tf32(hi.x));
        sm.mm.B[0][bks][bn8 + 1][bkl] = make_float2(to_tf32(lo.y), to_tf32(hi.y));
        sm.mm.B[0][bks][bn8 + 2][bkl] = make_float2(to_tf32(lo.z), to_tf32(hi.z));
        sm.mm.B[0][bks][bn8 + 3][bkl] = make_float2(to_tf32(lo.w), to_tf32(hi.w));
    }
    __syncthreads();

    int buf = 0;
#pragma unroll 1
    for (int ch = 0; ch < 24; ch++) {
        float4 va0, va1, lo, hi;
        const bool pf = (ch < 23);
        if (pf) {
            const int k0 = (ch + 1) * 16;
            va0 = *reinterpret_cast<const float4*>(Aptr0 + k0);
            va1 = *reinterpret_cast<const float4*>(Aptr1 + k0);
            const float* wr = W + (size_t)(k0 + bks * 8 + bkl) * 128 + bn8;
            lo = *reinterpret_cast<const float4*>(wr);
            hi = *reinterpret_cast<const float4*>(wr + 512);
        }
#pragma unroll
        for (int ks = 0; ks < 2; ks++) {
            const int kk = ks * 8;
            uint32_t a0 = __float_as_uint(sm.mm.A[buf][w * 16 + ly][kk + lx]);
            uint32_t a1 = __float_as_uint(sm.mm.A[buf][w * 16 + ly + 8][kk + lx]);
            uint32_t a2 = __float_as_uint(sm.mm.A[buf][w * 16 + ly][kk + lx + 4]);
            uint32_t a3 = __float_as_uint(sm.mm.A[buf][w * 16 + ly + 8][kk + lx + 4]);
#pragma unroll
            for (int nt = 0; nt < 16; nt++) {
                float2 b = sm.mm.B[buf][ks][nt * 8 + ly][lx];
                uint32_t b0 = __float_as_uint(b.x);
                uint32_t b1 = __float_as_uint(b.y);
                asm volatile(
                    "mma.sync.aligned.m16n8k8.row.col.f32.tf32.tf32.f32 "
                    "{%0,%1,%2,%3}, {%4,%5,%6,%7}, {%8,%9}, {%0,%1,%2,%3};"
                    : "+f"(acc[nt][0]), "+f"(acc[nt][1]),
                      "+f"(acc[nt][2]), "+f"(acc[nt][3])
                    : "r"(a0), "r"(a1), "r"(a2), "r"(a3), "r"(b0), "r"(b1));
            }
        }
        if (pf) {
            const int nb = buf ^ 1;
            sm.mm.A[nb][ar][ac + 0] = to_tf32(va0.x);
            sm.mm.A[nb][ar][ac + 1] = to_tf32(va0.y);
            sm.mm.A[nb][ar][ac + 2] = to_tf32(va0.z);
            sm.mm.A[nb][ar][ac + 3] = to_tf32(va0.w);
            sm.mm.A[nb][ar + 64][ac + 0] = to_tf32(va1.x);
            sm.mm.A[nb][ar + 64][ac + 1] = to_tf32(va1.y);
            sm.mm.A[nb][ar + 64][ac + 2] = to_tf32(va1.z);
            sm.mm.A[nb][ar + 64][ac + 3] = to_tf32(va1.w);
            sm.mm.B[nb][bks][bn8 + 0][bkl] = make_float2(to_tf32(lo.x), to_tf32(hi.x));
            sm.mm.B[nb][bks][bn8 + 1][bkl] = make_float2(to_tf32(lo.y), to_tf32(hi.y));
            sm.mm.B[nb][bks][bn8 + 2][bkl] = make_float2(to_tf32(lo.z), to_tf32(hi.z));
            sm.mm.B[nb][bks][bn8 + 3][bkl] = make_float2(to_tf32(lo.w), to_tf32(hi.w));
            __syncthreads();
            buf = nb;
        }
    }
    __syncthreads();   // staging smem no longer read; safe to overwrite with C

    // ---- epilogue: two 64-row passes through smem, warp-per-row LN ---------
    const int nc = lane * 4;
    const float4 gg  = *reinterpret_cast<const float4*>(gamma + nc);
    const float4 bbv = *reinterpret_cast<const float4*>(beta + nc);

#pragma unroll 1
    for (int p = 0; p < 2; p++) {
        if ((w >> 2) == p) {
            const int lbase = (w & 3) * 16;
#pragma unroll
            for (int nt = 0; nt < 16; nt++) {
                *reinterpret_cast<float2*>(&sm.C[lbase + ly][nt * 8 + 2 * lx]) =
                    make_float2(acc[nt][0], acc[nt][1]);
                *reinterpret_cast<float2*>(&sm.C[lbase + ly + 8][nt * 8 + 2 * lx]) =
                    make_float2(acc[nt][2], acc[nt][3]);
            }
        }
        __syncthreads();
#pragma unroll 1
        for (int rr = 0; rr < 8; rr++) {
            const int lr   = w * 8 + rr;
            const int gm   = bm + p * 64 + lr;
            const int node = gm % NNODE;
            float4 cv  = *reinterpret_cast<const float4*>(&sm.C[lr][nc]);
            float4 ctv = *reinterpret_cast<const float4*>(Ct + (size_t)node * 128 + nc);
            float4 hv  = *reinterpret_cast<const float4*>(H + (size_t)gm * 128 + nc);
            float x0 = hv.x + fmaxf(cv.x + ctv.x, 0.f);
            float x1 = hv.y + fmaxf(cv.y + ctv.y, 0.f);
            float x2 = hv.z + fmaxf(cv.z + ctv.z, 0.f);
            float x3 = hv.w + fmaxf(cv.w + ctv.w, 0.f);

            float s = x0 + x1 + x2 + x3;
#pragma unroll
            for (int o = 16; o > 0; o >>= 1) s += __shfl_xor_sync(0xffffffffu, s, o);
            float mu = s * (1.f / 128.f);

            float d0 = x0 - mu, d1 = x1 - mu, d2 = x2 - mu, d3 = x3 - mu;
            float q = d0 * d0 + d1 * d1 + d2 * d2 + d3 * d3;
#pragma unroll
            for (int o = 16; o > 0; o >>= 1) q += __shfl_xor_sync(0xffffffffu, q, o);
            float rstd = rsqrtf(q * (1.f / 128.f) + 1e-5f);

            float4 ov;
            ov.x = d0 * rstd * gg.x + bbv.x;
            ov.y = d1 * rstd * gg.y + bbv.y;
            ov.z = d2 * rstd * gg.z + bbv.z;
            ov.w = d3 * rstd * gg.w + bbv.w;
            *reinterpret_cast<float4*>(out + (size_t)gm * 128 + nc) = ov;
        }
        __syncthreads();
    }
}

// ---------------- CSR build --------------------------------------------------
__global__ void zero_deg_kernel(int* __restrict__ deg)
{
    int i = blockIdx.x * blockDim.x + threadIdx.x;
    if (i < NNODE) deg[i] = 0;
}

__global__ void hist_kernel(const int* __restrict__ ei0,
                            const int* __restrict__ ei1,
                            const int* __restrict__ ei2,
                            int* __restrict__ deg)
{
    int i = blockIdx.x * blockDim.x + threadIdx.x;
    if (i >= NEDGE_TOT) return;
    int r = i / NE, e = i - r * NE;
    const int* ei = (r == 0) ? ei0 : (r == 1) ? ei1 : ei2;
    atomicAdd(deg + ei[NE + e], 1);
}

__global__ __launch_bounds__(256)
void scan_kernel(const int* __restrict__ deg, int* __restrict__ off,
                 int* __restrict__ cursor)
{
    __shared__ int warp_sums[8];
    __shared__ int s_carry;
    const int tid  = threadIdx.x;
    const int lane = tid & 31;
    const int wid  = tid >> 5;
    if (tid == 0) s_carry = 0;
    __syncthreads();

    for (int base = 0; base < NNODE; base += 256) {
        int i = base + tid;
        int x = (i < NNODE) ? deg[i] : 0;
        int v = x;
#pragma unroll
        for (int d = 1; d < 32; d <<= 1) {
            int t = __shfl_up_sync(0xffffffffu, v, d);
            if (lane >= d) v += t;
        }
        if (lane == 31) warp_sums[wid] = v;
        __syncthreads();
        if (wid == 0 && lane < 8) {
            int s = warp_sums[lane];
#pragma unroll
            for (int d = 1; d < 8; d <<= 1) {
                int t = __shfl_up_sync(0x000000ffu, s, d);
                if (lane >= d) s += t;
            }
            warp_sums[lane] = s;
        }
        __syncthreads();
        int add  = (wid > 0) ? warp_sums[wid - 1] : 0;
        int incl = v + add + s_carry;
        if (i < NNODE) { off[i] = incl - x; cursor[i] = incl - x; }
        __syncthreads();
        if (tid == 255) s_carry = incl;
        __syncthreads();
    }
    if (tid == 0) off[NNODE] = s_carry;
}

__global__ void fill_kernel(const int* __restrict__ ei0,
                            const int* __restrict__ ei1,
                            const int* __restrict__ ei2,
                            int* __restrict__ cursor,
                            int2* __restrict__ entries)
{
    int i = blockIdx.x * blockDim.x + threadIdx.x;
    if (i >= NEDGE_TOT) return;
    int r = i / NE, e = i - r * NE;
    const int* ei = (r == 0) ? ei0 : (r == 1) ? ei1 : ei2;
    int src = ei[e];
    int dst = ei[NE + e];
    int pos = atomicAdd(cursor + dst, 1);
    entries[pos] = make_int2(src, (r << 20) | e);
}

// ---------------- per-node stats: counts + edge-attr sums -------------------
__global__ __launch_bounds__(256)
void stats_kernel(const int* __restrict__ off, const int2* __restrict__ entries,
                  const float* __restrict__ ea0, const float* __restrict__ ea1,
                  float* __restrict__ S0, float* __restrict__ S1,
                  float* __restrict__ cnt)
{
    int warp = (blockIdx.x * blockDim.x + threadIdx.x) >> 5;
    int lane = threadIdx.x & 31;
    if (warp >= NNODE) return;
    const int jb = off[warp], je = off[warp + 1];
    float s0 = 0.f, s1 = 0.f;
    int c0 = 0, c1 = 0, c2 = 0;
    for (int j = jb; j < je; j++) {
        int2 m = entries[j];
        int rel = m.y >> 20, e = m.y & 0xFFFFF;
        if (rel == 0)      { c0++; if (lane < 16) s0 += ea0[(size_t)e * 16 + lane]; }
        else if (rel == 1) { c1++; if (lane < 16) s1 += ea1[(size_t)e * 16 + lane]; }
        else               { c2++; }
    }
    if (lane < 16) {
        S0[(size_t)warp * 16 + lane] = s0;
        S1[(size_t)warp * 16 + lane] = s1;
    }
    if (lane == 0) {
        cnt[(size_t)warp * 4 + 0] = (float)c0;
        cnt[(size_t)warp * 4 + 1] = (float)c1;
        cnt[(size_t)warp * 4 + 2] = (float)c2;
    }
}

// ---------------- Cterm: per-node, per-layer constant term ------------------
#define CT_NODES 16
__global__ __launch_bounds__(128)
void cterm_kernel(const float* __restrict__ S0, const float* __restrict__ S1,
                  const float* __restrict__ cnt,
                  const float* __restrict__ node_b, const float* __restrict__ edge_W,
                  const float* __restrict__ edge_b, float* __restrict__ Ct)
{
    const int l   = blockIdx.y;
    const int j   = threadIdx.x;
    __shared__ float eW0[16 * 128];
    __shared__ float eW1[16 * 128];
    __shared__ float nb0[128], nb1[128], nb2[128], eb0[128], eb1[128];
    __shared__ float sS[2][32];

    for (int k = 0; k < 16; k++) {
        eW0[k * 128 + j] = edge_W[((size_t)(l * 2 + 0) * 16 + k) * 128 + j];
        eW1[k * 128 + j] = edge_W[((size_t)(l * 2 + 1) * 16 + k) * 128 + j];
    }
    nb0[j] = node_b[(size_t)(l * 3 + 0) * 128 + j];
    nb1[j] = node_b[(size_t)(l * 3 + 1) * 128 + j];
    nb2[j] = node_b[(size_t)(l * 3 + 2) * 128 + j];
    eb0[j] = edge_b[(size_t)(l * 2 + 0) * 128 + j];
    eb1[j] = edge_b[(size_t)(l * 2 + 1) * 128 + j];
    __syncthreads();

    const int nbase = blockIdx.x * CT_NODES;
    for (int t = 0; t < CT_NODES; t++) {
        int node = nbase + t;
        int buf = t & 1;
        if (j < 16)      sS[buf][j] = S0[(size_t)node * 16 + j];
        else if (j < 32) sS[buf][j] = S1[(size_t)node * 16 + (j - 16)];
        __syncthreads();
        float c0 = cnt[(size_t)node * 4 + 0];
        float c1 = cnt[(size_t)node * 4 + 1];
        float c2 = cnt[(size_t)node * 4 + 2];
        float v = c0 * (nb0[j] + eb0[j]) + c1 * (nb1[j] + eb1[j]) + c2 * nb2[j];
#pragma unroll
        for (int k = 0; k < 16; k++) v = fmaf(sS[buf][k], eW0[k * 128 + j], v);
#pragma unroll
        for (int k = 0; k < 16; k++) v = fmaf(sS[buf][k + 16], eW1[k * 128 + j], v);
        Ct[((size_t)l * NNODE + node) * 128 + j] = v;
        __syncthreads();
    }
}

// ---------------- gather: G[b,node, r*128:...] = sum H[b,src] over r-edges --
__global__ __launch_bounds__(256)
void gather_kernel(const float* __restrict__ H, const int* __restrict__ off,
                   const int2* __restrict__ entries, float* __restrict__ G)
{
    int warp = (blockIdx.x * blockDim.x + threadIdx.x) >> 5;
    int lane = threadIdx.x & 31;
    if (warp >= NNODE) return;
    const int node = warp;
    const int jb = off[node], je = off[node + 1];

    float4 a0[BATCH], a1[BATCH], a2[BATCH];
#pragma unroll
    for (int b = 0; b < BATCH; b++) {
        a0[b] = make_float4(0.f, 0.f, 0.f, 0.f);
        a1[b] = make_float4(0.f, 0.f, 0.f, 0.f);
        a2[b] = make_float4(0.f, 0.f, 0.f, 0.f);
    }

    for (int j = jb; j < je; j++) {
        int2 m = entries[j];
        int src = m.x;
        int rel = m.y >> 20;
        const float* hb = H + (size_t)src * 128 + lane * 4;
        float4 h[BATCH];
#pragma unroll
        for (int b = 0; b < BATCH; b++)
            h[b] = *reinterpret_cast<const float4*>(hb + (size_t)b * NNODE * 128);
        if (rel == 0) {
#pragma unroll
            for (int b = 0; b < BATCH; b++) {
                a0[b].x += h[b].x; a0[b].y += h[b].y; a0[b].z += h[b].z; a0[b].w += h[b].w;
            }
        } else if (rel == 1) {
#pragma unroll
            for (int b = 0; b < BATCH; b++) {
                a1[b].x += h[b].x; a1[b].y += h[b].y; a1[b].z += h[b].z; a1[b].w += h[b].w;
            }
        } else {
#pragma unroll
            for (int b = 0; b < BATCH; b++) {
                a2[b].x += h[b].x; a2[b].y += h[b].y; a2[b].z += h[b].z; a2[b].w += h[b].w;
            }
        }
    }

#pragma unroll
    for (int b = 0; b < BATCH; b++) {
        float* gb = G + (size_t)(b * NNODE + node) * 384 + lane * 4;
        *reinterpret_cast<float4*>(gb)       = a0[b];
        *reinterpret_cast<float4*>(gb + 128) = a1[b];
        *reinterpret_cast<float4*>(gb + 256) = a2[b];
    }
}

// ---------------- launch -----------------------------------------------------
extern "C" void kernel_launch(void* const* d_in, const int* in_sizes, int n_in,
                              void* d_out, int out_size)
{
    const float* node_feat = (const float*)d_in[0];
    const float* in_W      = (const float*)d_in[1];
    const float* in_b      = (const float*)d_in[2];
    const float* node_W    = (const float*)d_in[3];
    const float* node_b    = (const float*)d_in[4];
    const float* edge_W    = (const float*)d_in[5];
    const float* edge_b    = (const float*)d_in[6];
    const float* ln_g      = (const float*)d_in[7];
    const float* ln_b      = (const float*)d_in[8];
    const float* ea0       = (const float*)d_in[9];
    const float* ea1       = (const float*)d_in[10];
    const int*   ei0       = (const int*)d_in[11];
    const int*   ei1       = (const int*)d_in[12];
    const int*   ei2       = (const int*)d_in[13];
    float* out = (float*)d_out;

    float *H, *G, *Ct, *S0, *S1, *cnt;
    int *deg, *off, *cursor;
    int2* entries;
    cudaGetSymbolAddress((void**)&H,       g_H);
    cudaGetSymbolAddress((void**)&G,       g_G);
    cudaGetSymbolAddress((void**)&Ct,      g_Cterm);
    cudaGetSymbolAddress((void**)&S0,      g_S0);
    cudaGetSymbolAddress((void**)&S1,      g_S1);
    cudaGetSymbolAddress((void**)&cnt,     g_cnt);
    cudaGetSymbolAddress((void**)&deg,     g_deg);
    cudaGetSymbolAddress((void**)&off,     g_off);
    cudaGetSymbolAddress((void**)&cursor,  g_cursor);
    cudaGetSymbolAddress((void**)&entries, g_entries);

    // CSR + per-node stats + per-layer constant terms
    zero_deg_kernel<<<(NNODE + 255) / 256, 256>>>(deg);
    hist_kernel<<<(NEDGE_TOT + 255) / 256, 256>>>(ei0, ei1, ei2, deg);
    scan_kernel<<<1, 256>>>(deg, off, cursor);
    fill_kernel<<<(NEDGE_TOT + 255) / 256, 256>>>(ei0, ei1, ei2, cursor, entries);
    stats_kernel<<<(NNODE * 32 + 255) / 256, 256>>>(off, entries, ea0, ea1, S0, S1, cnt);
    {
        dim3 grid(NNODE / CT_NODES, NL);
        cterm_kernel<<<grid, 128>>>(S0, S1, cnt, node_b, edge_W, edge_b, Ct);
    }

    // input projection (fp32 for accurate base H)
    sgemm128<<<(ROWS + 127) / 128, 256>>>(node_feat, in_W, in_b, H, ROWS, DN, DM, 0);

    for (int l = 0; l < NL; l++) {
        gather_kernel<<<(NNODE * 32 + 255) / 256, 256>>>(H, off, entries, G);
        float* dst = (l == NL - 1) ? out : H;
        gemm_ln_tf32<<<ROWS / 128, 256>>>(
            G, node_W + (size_t)l * 3 * DM * DM, H, Ct + (size_t)l * NNODE * DM,
            ln_g + (size_t)l * DM, ln_b + (size_t)l * DM, dst);
    }
}

// round 6
// speedup vs baseline: 1.9275x; 1.1111x over previous
#include <cuda_runtime.h>
#include <cstdint>

#define BATCH 4
#define NNODE 20000
#define DN 64
#define DM 128
#define NE 160000
#define NL 2
#define ROWS (BATCH*NNODE)   // 80000
#define NEDGE_TOT (3*NE)     // 480000

// ---------------- scratch (device globals) ----------------------------------
__device__ float  g_H[(size_t)ROWS * DM];            // 41 MB
__device__ float  g_G[(size_t)ROWS * 3 * DM];        // 123 MB (tf32-rounded)
__device__ float  g_Cterm[(size_t)NL * NNODE * DM];  // 20.5 MB
__device__ float2 g_Wpre[(size_t)NL * 24576];        // B-fragment images
__device__ float  g_S0[(size_t)NNODE * 16];
__device__ float  g_S1[(size_t)NNODE * 16];
__device__ float  g_cnt[(size_t)NNODE * 4];
__device__ int    g_deg[NNODE];
__device__ int    g_off[NNODE + 1];
__device__ int    g_cursor[NNODE];
__device__ int2   g_entries[NEDGE_TOT];

__device__ __forceinline__ float to_tf32(float x) {
    uint32_t u;
    asm("cvt.rna.tf32.f32 %0, %1;" : "=r"(u) : "f"(x));
    return __uint_as_float(u);
}

__device__ __forceinline__ void cp16(void* dst, const void* src) {
    uint32_t d = (uint32_t)__cvta_generic_to_shared(dst);
    asm volatile("cp.async.cg.shared.global [%0], [%1], 16;" :: "r"(d), "l"(src));
}
__device__ __forceinline__ void cp_commit() {
    asm volatile("cp.async.commit_group;");
}
__device__ __forceinline__ void cp_wait0() {
    asm volatile("cp.async.wait_group 0;");
}

// ---------------- fp32 SGEMM (inproj only, K=64) -----------------------------
__global__ __launch_bounds__(256)
void sgemm128(const float* __restrict__ A, const float* __restrict__ W,
              const float* __restrict__ bias, float* __restrict__ C,
              int M, int K, int ldc, int coff)
{
    __shared__ float As[2][8][128];
    __shared__ float Bs[2][8][128];
    const int bm  = blockIdx.x * 128;
    const int tid = threadIdx.x;
    const int tx  = tid & 15;
    const int ty  = tid >> 4;

    float acc[8][8];
#pragma unroll
    for (int i = 0; i < 8; i++)
#pragma unroll
        for (int j = 0; j < 8; j++) acc[i][j] = 0.f;

    const int lm  = tid >> 1;
    const int lk4 = (tid & 1) * 4;
    const int lkB = tid >> 5;
    const int lnB = (tid & 31) * 4;
    const bool arow_ok = (bm + lm) < M;
    const float* Aptr = A + (size_t)(bm + lm) * K + lk4;

    float4 av = make_float4(0.f, 0.f, 0.f, 0.f);
    if (arow_ok) av = *reinterpret_cast<const float4*>(Aptr);
    float4 bv = *reinterpret_cast<const float4*>(W + (size_t)lkB * 128 + lnB);
    As[0][lk4 + 0][lm] = av.x; As[0][lk4 + 1][lm] = av.y;
    As[0][lk4 + 2][lm] = av.z; As[0][lk4 + 3][lm] = av.w;
    *reinterpret_cast<float4*>(&Bs[0][lkB][lnB]) = bv;
    __syncthreads();

    int cur = 0;
    for (int k0 = 8; k0 < K; k0 += 8) {
        av = make_float4(0.f, 0.f, 0.f, 0.f);
        if (arow_ok) av = *reinterpret_cast<const float4*>(Aptr + k0);
        bv = *reinterpret_cast<const float4*>(W + (size_t)(k0 + lkB) * 128 + lnB);
#pragma unroll
        for (int kk = 0; kk < 8; kk++) {
            float a[8], b[8];
#pragma unroll
            for (int i = 0; i < 8; i++) a[i] = As[cur][kk][ty * 8 + i];
#pragma unroll
            for (int j = 0; j < 8; j++) b[j] = Bs[cur][kk][tx * 8 + j];
#pragma unroll
            for (int i = 0; i < 8; i++)
#pragma unroll
                for (int j = 0; j < 8; j++)
                    acc[i][j] = fmaf(a[i], b[j], acc[i][j]);
        }
        int nxt = cur ^ 1;
        As[nxt][lk4 + 0][lm] = av.x; As[nxt][lk4 + 1][lm] = av.y;
        As[nxt][lk4 + 2][lm] = av.z; As[nxt][lk4 + 3][lm] = av.w;
        *reinterpret_cast<float4*>(&Bs[nxt][lkB][lnB]) = bv;
        __syncthreads();
        cur = nxt;
    }
#pragma unroll
    for (int kk = 0; kk < 8; kk++) {
        float a[8], b[8];
#pragma unroll
        for (int i = 0; i < 8; i++) a[i] = As[cur][kk][ty * 8 + i];
#pragma unroll
        for (int j = 0; j < 8; j++) b[j] = Bs[cur][kk][tx * 8 + j];
#pragma unroll
        for (int i = 0; i < 8; i++)
#pragma unroll
            for (int j = 0; j < 8; j++)
                acc[i][j] = fmaf(a[i], b[j], acc[i][j]);
    }
#pragma unroll
    for (int i = 0; i < 8; i++) {
        int gm = bm + ty * 8 + i;
        if (gm < M) {
#pragma unroll
            for (int j = 0; j < 8; j += 4) {
                int n = tx * 8 + j;
                float4 o;
                o.x = acc[i][j + 0] + bias[n + 0];
                o.y = acc[i][j + 1] + bias[n + 1];
                o.z = acc[i][j + 2] + bias[n + 2];
                o.w = acc[i][j + 3] + bias[n + 3];
                *reinterpret_cast<float4*>(C + (size_t)gm * ldc + coff + n) = o;
            }
        }
    }
}

// ---------------- W pre-conversion to B-fragment smem image -----------------
// Wpre[l] flat float2 index: ((ch*2+ks)*128+n)*4 + kl  = (W[k][n], W[k+4][n]) tf32
__global__ void prep_w_kernel(const float* __restrict__ node_W,
                              float2* __restrict__ Wpre)
{
    int idx = blockIdx.x * blockDim.x + threadIdx.x;
    if (idx >= NL * 24576) return;
    int l   = idx / 24576;
    int r   = idx % 24576;
    int ch  = r >> 10;
    int ks  = (r >> 9) & 1;
    int n   = (r >> 2) & 127;
    int kl  = r & 3;
    int k   = ch * 16 + ks * 8 + kl;
    const float* W = node_W + (size_t)l * 3 * DM * DM;   // [384][128]
    float lo = to_tf32(W[(size_t)k * 128 + n]);
    float hi = to_tf32(W[(size_t)(k + 4) * 128 + n]);
    Wpre[idx] = make_float2(lo, hi);
}

// ---------------- tf32 tensor-core fused GEMM + Cterm + relu + H + LN -------
// out[row] = LN( H[row] + relu( G[row,0:384] @ W[384x128] + Ct[row%NNODE] ) )
// cp.async double-buffered; A,B pre-converted to tf32 upstream.
__global__ __launch_bounds__(256)
void gemm_ln_tf32(const float* __restrict__ G, const float2* __restrict__ Wpre,
                  const float* __restrict__ H, const float* __restrict__ Ct,
                  const float* __restrict__ gamma, const float* __restrict__ beta,
                  float* __restrict__ out)
{
    // stage layout per buffer:
    //   A = 128 rows x 20 floats (16 data + 4 pad) = 10240 B
    //   B = [ks(2)][n(128)][4 float2] stride 32B (no pad)  = 8192 B
    __shared__ union SmemU {
        char  raw[2][18432];
        float C[64][132];
    } sm;

    const int tid  = threadIdx.x;
    const int bm   = blockIdx.x * 128;
    const int w    = tid >> 5;
    const int lane = tid & 31;
    const int ly   = lane >> 2;
    const int lx   = lane & 3;

    // staging indices (4 cp16/thread/chunk)
    const int arow = tid >> 1;              // A row
    const int aseg = (tid & 1) * 2;         // A segs {0,1} or {2,3}
    const int bks  = tid >> 7;              // B ks
    const int bn   = tid & 127;             // B n
    const float* Arow = G + (size_t)(bm + arow) * 384 + aseg * 4;
    const char*  Wp   = reinterpret_cast<const char*>(Wpre) + ((size_t)bks * 128 + bn) * 32;

    float acc[16][4];
#pragma unroll
    for (int nt = 0; nt < 16; nt++)
#pragma unroll
        for (int j = 0; j < 4; j++) acc[nt][j] = 0.f;

    auto stage = [&](int s, int ch) {
        char* A = sm.raw[s];
        char* B = sm.raw[s] + 10240;
        cp16(A + arow * 80 + aseg * 16,      Arow + ch * 16);
        cp16(A + arow * 80 + aseg * 16 + 16, Arow + ch * 16 + 4);
        const char* src = Wp + (size_t)ch * 8192;
        cp16(B + bks * 4096 + bn * 32,      src);
        cp16(B + bks * 4096 + bn * 32 + 16, src + 16);
    };

    stage(0, 0);
    cp_commit();

    int buf = 0;
#pragma unroll 1
    for (int ch = 0; ch < 24; ch++) {
        cp_wait0();
        __syncthreads();
        if (ch + 1 < 24) { stage(buf ^ 1, ch + 1); cp_commit(); }

        const float* A = reinterpret_cast<const float*>(sm.raw[buf]);
        const char*  B = sm.raw[buf] + 10240;
#pragma unroll
        for (int ks = 0; ks < 2; ks++) {
            const int kk = ks * 8;
            uint32_t a0 = __float_as_uint(A[(w * 16 + ly) * 20 + kk + lx]);
            uint32_t a1 = __float_as_uint(A[(w * 16 + ly + 8) * 20 + kk + lx]);
            uint32_t a2 = __float_as_uint(A[(w * 16 + ly) * 20 + kk + lx + 4]);
            uint32_t a3 = __float_as_uint(A[(w * 16 + ly + 8) * 20 + kk + lx + 4]);
#pragma unroll
            for (int nt = 0; nt < 16; nt++) {
                float2 b = *reinterpret_cast<const float2*>(
                    B + ks * 4096 + (nt * 8 + ly) * 32 + lx * 8);
                uint32_t b0 = __float_as_uint(b.x);
                uint32_t b1 = __float_as_uint(b.y);
                asm volatile(
                    "mma.sync.aligned.m16n8k8.row.col.f32.tf32.tf32.f32 "
                    "{%0,%1,%2,%3}, {%4,%5,%6,%7}, {%8,%9}, {%0,%1,%2,%3};"
                    : "+f"(acc[nt][0]), "+f"(acc[nt][1]),
                      "+f"(acc[nt][2]), "+f"(acc[nt][3])
                    : "r"(a0), "r"(a1), "r"(a2), "r"(a3), "r"(b0), "r"(b1));
            }
        }
        buf ^= 1;
    }
    __syncthreads();   // staging smem no longer read; safe to overwrite with C

    // ---- epilogue: two 64-row passes through smem, warp-per-row LN ---------
    const int nc = lane * 4;
    const float4 gg  = *reinterpret_cast<const float4*>(gamma + nc);
    const float4 bbv = *reinterpret_cast<const float4*>(beta + nc);

#pragma unroll 1
    for (int p = 0; p < 2; p++) {
        if ((w >> 2) == p) {
            const int lbase = (w & 3) * 16;
#pragma unroll
            for (int nt = 0; nt < 16; nt++) {
                *reinterpret_cast<float2*>(&sm.C[lbase + ly][nt * 8 + 2 * lx]) =
                    make_float2(acc[nt][0], acc[nt][1]);
                *reinterpret_cast<float2*>(&sm.C[lbase + ly + 8][nt * 8 + 2 * lx]) =
                    make_float2(acc[nt][2], acc[nt][3]);
            }
        }
        __syncthreads();
#pragma unroll 1
        for (int rr = 0; rr < 8; rr++) {
            const int lr   = w * 8 + rr;
            const int gm   = bm + p * 64 + lr;
            const int node = gm % NNODE;
            float4 cv  = *reinterpret_cast<const float4*>(&sm.C[lr][nc]);
            float4 ctv = *reinterpret_cast<const float4*>(Ct + (size_t)node * 128 + nc);
            float4 hv  = *reinterpret_cast<const float4*>(H + (size_t)gm * 128 + nc);
            float x0 = hv.x + fmaxf(cv.x + ctv.x, 0.f);
            float x1 = hv.y + fmaxf(cv.y + ctv.y, 0.f);
            float x2 = hv.z + fmaxf(cv.z + ctv.z, 0.f);
            float x3 = hv.w + fmaxf(cv.w + ctv.w, 0.f);

            float s = x0 + x1 + x2 + x3;
#pragma unroll
            for (int o = 16; o > 0; o >>= 1) s += __shfl_xor_sync(0xffffffffu, s, o);
            float mu = s * (1.f / 128.f);

            float d0 = x0 - mu, d1 = x1 - mu, d2 = x2 - mu, d3 = x3 - mu;
            float q = d0 * d0 + d1 * d1 + d2 * d2 + d3 * d3;
#pragma unroll
            for (int o = 16; o > 0; o >>= 1) q += __shfl_xor_sync(0xffffffffu, q, o);
            float rstd = rsqrtf(q * (1.f / 128.f) + 1e-5f);

            float4 ov;
            ov.x = d0 * rstd * gg.x + bbv.x;
            ov.y = d1 * rstd * gg.y + bbv.y;
            ov.z = d2 * rstd * gg.z + bbv.z;
            ov.w = d3 * rstd * gg.w + bbv.w;
            *reinterpret_cast<float4*>(out + (size_t)gm * 128 + nc) = ov;
        }
        __syncthreads();
    }
}

// ---------------- CSR build --------------------------------------------------
__global__ void zero_deg_kernel(int* __restrict__ deg)
{
    int i = blockIdx.x * blockDim.x + threadIdx.x;
    if (i < NNODE) deg[i] = 0;
}

__global__ void hist_kernel(const int* __restrict__ ei0,
                            const int* __restrict__ ei1,
                            const int* __restrict__ ei2,
                            int* __restrict__ deg)
{
    int i = blockIdx.x * blockDim.x + threadIdx.x;
    if (i >= NEDGE_TOT) return;
    int r = i / NE, e = i - r * NE;
    const int* ei = (r == 0) ? ei0 : (r == 1) ? ei1 : ei2;
    atomicAdd(deg + ei[NE + e], 1);
}

__global__ __launch_bounds__(256)
void scan_kernel(const int* __restrict__ deg, int* __restrict__ off,
                 int* __restrict__ cursor)
{
    __shared__ int warp_sums[8];
    __shared__ int s_carry;
    const int tid  = threadIdx.x;
    const int lane = tid & 31;
    const int wid  = tid >> 5;
    if (tid == 0) s_carry = 0;
    __syncthreads();

    for (int base = 0; base < NNODE; base += 256) {
        int i = base + tid;
        int x = (i < NNODE) ? deg[i] : 0;
        int v = x;
#pragma unroll
        for (int d = 1; d < 32; d <<= 1) {
            int t = __shfl_up_sync(0xffffffffu, v, d);
            if (lane >= d) v += t;
        }
        if (lane == 31) warp_sums[wid] = v;
        __syncthreads();
        if (wid == 0 && lane < 8) {
            int s = warp_sums[lane];
#pragma unroll
            for (int d = 1; d < 8; d <<= 1) {
                int t = __shfl_up_sync(0x000000ffu, s, d);
                if (lane >= d) s += t;
            }
            warp_sums[lane] = s;
        }
        __syncthreads();
        int add  = (wid > 0) ? warp_sums[wid - 1] : 0;
        int incl = v + add + s_carry;
        if (i < NNODE) { off[i] = incl - x; cursor[i] = incl - x; }
        __syncthreads();
        if (tid == 255) s_carry = incl;
        __syncthreads();
    }
    if (tid == 0) off[NNODE] = s_carry;
}

__global__ void fill_kernel(const int* __restrict__ ei0,
                            const int* __restrict__ ei1,
                            const int* __restrict__ ei2,
                            int* __restrict__ cursor,
                            int2* __restrict__ entries)
{
    int i = blockIdx.x * blockDim.x + threadIdx.x;
    if (i >= NEDGE_TOT) return;
    int r = i / NE, e = i - r * NE;
    const int* ei = (r == 0) ? ei0 : (r == 1) ? ei1 : ei2;
    int src = ei[e];
    int dst = ei[NE + e];
    int pos = atomicAdd(cursor + dst, 1);
    entries[pos] = make_int2(src, (r << 20) | e);
}

// ---------------- per-node stats: counts + edge-attr sums -------------------
__global__ __launch_bounds__(256)
void stats_kernel(const int* __restrict__ off, const int2* __restrict__ entries,
                  const float* __restrict__ ea0, const float* __restrict__ ea1,
                  float* __restrict__ S0, float* __restrict__ S1,
                  float* __restrict__ cnt)
{
    int warp = (blockIdx.x * blockDim.x + threadIdx.x) >> 5;
    int lane = threadIdx.x & 31;
    if (warp >= NNODE) return;
    const int jb = off[warp], je = off[warp + 1];
    float s0 = 0.f, s1 = 0.f;
    int c0 = 0, c1 = 0, c2 = 0;
    for (int j = jb; j < je; j++) {
        int2 m = entries[j];
        int rel = m.y >> 20, e = m.y & 0xFFFFF;
        if (rel == 0)      { c0++; if (lane < 16) s0 += ea0[(size_t)e * 16 + lane]; }
        else if (rel == 1) { c1++; if (lane < 16) s1 += ea1[(size_t)e * 16 + lane]; }
        else               { c2++; }
    }
    if (lane < 16) {
        S0[(size_t)warp * 16 + lane] = s0;
        S1[(size_t)warp * 16 + lane] = s1;
    }
    if (lane == 0) {
        cnt[(size_t)warp * 4 + 0] = (float)c0;
        cnt[(size_t)warp * 4 + 1] = (float)c1;
        cnt[(size_t)warp * 4 + 2] = (float)c2;
    }
}

// ---------------- Cterm: per-node, per-layer constant term ------------------
#define CT_NODES 16
__global__ __launch_bounds__(128)
void cterm_kernel(const float* __restrict__ S0, const float* __restrict__ S1,
                  const float* __restrict__ cnt,
                  const float* __restrict__ node_b, const float* __restrict__ edge_W,
                  const float* __restrict__ edge_b, float* __restrict__ Ct)
{
    const int l   = blockIdx.y;
    const int j   = threadIdx.x;
    __shared__ float eW0[16 * 128];
    __shared__ float eW1[16 * 128];
    __shared__ float nb0[128], nb1[128], nb2[128], eb0[128], eb1[128];
    __shared__ float sS[2][32];

    for (int k = 0; k < 16; k++) {
        eW0[k * 128 + j] = edge_W[((size_t)(l * 2 + 0) * 16 + k) * 128 + j];
        eW1[k * 128 + j] = edge_W[((size_t)(l * 2 + 1) * 16 + k) * 128 + j];
    }
    nb0[j] = node_b[(size_t)(l * 3 + 0) * 128 + j];
    nb1[j] = node_b[(size_t)(l * 3 + 1) * 128 + j];
    nb2[j] = node_b[(size_t)(l * 3 + 2) * 128 + j];
    eb0[j] = edge_b[(size_t)(l * 2 + 0) * 128 + j];
    eb1[j] = edge_b[(size_t)(l * 2 + 1) * 128 + j];
    __syncthreads();

    const int nbase = blockIdx.x * CT_NODES;
    for (int t = 0; t < CT_NODES; t++) {
        int node = nbase + t;
        int buf = t & 1;
        if (j < 16)      sS[buf][j] = S0[(size_t)node * 16 + j];
        else if (j < 32) sS[buf][j] = S1[(size_t)node * 16 + (j - 16)];
        __syncthreads();
        float c0 = cnt[(size_t)node * 4 + 0];
        float c1 = cnt[(size_t)node * 4 + 1];
        float c2 = cnt[(size_t)node * 4 + 2];
        float v = c0 * (nb0[j] + eb0[j]) + c1 * (nb1[j] + eb1[j]) + c2 * nb2[j];
#pragma unroll
        for (int k = 0; k < 16; k++) v = fmaf(sS[buf][k], eW0[k * 128 + j], v);
#pragma unroll
        for (int k = 0; k < 16; k++) v = fmaf(sS[buf][k + 16], eW1[k * 128 + j], v);
        Ct[((size_t)l * NNODE + node) * 128 + j] = v;
        __syncthreads();
    }
}

// ---------------- gather: G[b,node, r*128:...] = sum H[b,src] (tf32 out) ----
__global__ __launch_bounds__(256)
void gather_kernel(const float* __restrict__ H, const int* __restrict__ off,
                   const int2* __restrict__ entries, float* __restrict__ G)
{
    int warp = (blockIdx.x * blockDim.x + threadIdx.x) >> 5;
    int lane = threadIdx.x & 31;
    if (warp >= NNODE) return;
    const int node = warp;
    const int jb = off[node], je = off[node + 1];

    float4 a0[BATCH], a1[BATCH], a2[BATCH];
#pragma unroll
    for (int b = 0; b < BATCH; b++) {
        a0[b] = make_float4(0.f, 0.f, 0.f, 0.f);
        a1[b] = make_float4(0.f, 0.f, 0.f, 0.f);
        a2[b] = make_float4(0.f, 0.f, 0.f, 0.f);
    }

    for (int j = jb; j < je; j++) {
        int2 m = entries[j];
        int src = m.x;
        int rel = m.y >> 20;
        const float* hb = H + (size_t)src * 128 + lane * 4;
        float4 h[BATCH];
#pragma unroll
        for (int b = 0; b < BATCH; b++)
            h[b] = *reinterpret_cast<const float4*>(hb + (size_t)b * NNODE * 128);
        if (rel == 0) {
#pragma unroll
            for (int b = 0; b < BATCH; b++) {
                a0[b].x += h[b].x; a0[b].y += h[b].y; a0[b].z += h[b].z; a0[b].w += h[b].w;
            }
        } else if (rel == 1) {
#pragma unroll
            for (int b = 0; b < BATCH; b++) {
                a1[b].x += h[b].x; a1[b].y += h[b].y; a1[b].z += h[b].z; a1[b].w += h[b].w;
            }
        } else {
#pragma unroll
            for (int b = 0; b < BATCH; b++) {
                a2[b].x += h[b].x; a2[b].y += h[b].y; a2[b].z += h[b].z; a2[b].w += h[b].w;
            }
        }
    }

#pragma unroll
    for (int b = 0; b < BATCH; b++) {
        float* gb = G + (size_t)(b * NNODE + node) * 384 + lane * 4;
        float4 v0 = make_float4(to_tf32(a0[b].x), to_tf32(a0[b].y), to_tf32(a0[b].z), to_tf32(a0[b].w));
        float4 v1 = make_float4(to_tf32(a1[b].x), to_tf32(a1[b].y), to_tf32(a1[b].z), to_tf32(a1[b].w));
        float4 v2 = make_float4(to_tf32(a2[b].x), to_tf32(a2[b].y), to_tf32(a2[b].z), to_tf32(a2[b].w));
        *reinterpret_cast<float4*>(gb)       = v0;
        *reinterpret_cast<float4*>(gb + 128) = v1;
        *reinterpret_cast<float4*>(gb + 256) = v2;
    }
}

// ---------------- launch -----------------------------------------------------
extern "C" void kernel_launch(void* const* d_in, const int* in_sizes, int n_in,
                              void* d_out, int out_size)
{
    const float* node_feat = (const float*)d_in[0];
    const float* in_W      = (const float*)d_in[1];
    const float* in_b      = (const float*)d_in[2];
    const float* node_W    = (const float*)d_in[3];
    const float* node_b    = (const float*)d_in[4];
    const float* edge_W    = (const float*)d_in[5];
    const float* edge_b    = (const float*)d_in[6];
    const float* ln_g      = (const float*)d_in[7];
    const float* ln_b      = (const float*)d_in[8];
    const float* ea0       = (const float*)d_in[9];
    const float* ea1       = (const float*)d_in[10];
    const int*   ei0       = (const int*)d_in[11];
    const int*   ei1       = (const int*)d_in[12];
    const int*   ei2       = (const int*)d_in[13];
    float* out = (float*)d_out;

    float *H, *G, *Ct, *S0, *S1, *cnt;
    float2* Wpre;
    int *deg, *off, *cursor;
    int2* entries;
    cudaGetSymbolAddress((void**)&H,       g_H);
    cudaGetSymbolAddress((void**)&G,       g_G);
    cudaGetSymbolAddress((void**)&Ct,      g_Cterm);
    cudaGetSymbolAddress((void**)&Wpre,    g_Wpre);
    cudaGetSymbolAddress((void**)&S0,      g_S0);
    cudaGetSymbolAddress((void**)&S1,      g_S1);
    cudaGetSymbolAddress((void**)&cnt,     g_cnt);
    cudaGetSymbolAddress((void**)&deg,     g_deg);
    cudaGetSymbolAddress((void**)&off,     g_off);
    cudaGetSymbolAddress((void**)&cursor,  g_cursor);
    cudaGetSymbolAddress((void**)&entries, g_entries);

    // CSR + per-node stats + per-layer constant terms + W pre-conversion
    zero_deg_kernel<<<(NNODE + 255) / 256, 256>>>(deg);
    hist_kernel<<<(NEDGE_TOT + 255) / 256, 256>>>(ei0, ei1, ei2, deg);
    scan_kernel<<<1, 256>>>(deg, off, cursor);
    fill_kernel<<<(NEDGE_TOT + 255) / 256, 256>>>(ei0, ei1, ei2, cursor, entries);
    stats_kernel<<<(NNODE * 32 + 255) / 256, 256>>>(off, entries, ea0, ea1, S0, S1, cnt);
    {
        dim3 grid(NNODE / CT_NODES, NL);
        cterm_kernel<<<grid, 128>>>(S0, S1, cnt, node_b, edge_W, edge_b, Ct);
    }
    prep_w_kernel<<<(NL * 24576 + 255) / 256, 256>>>(node_W, Wpre);

    // input projection (fp32 for accurate base H)
    sgemm128<<<(ROWS + 127) / 128, 256>>>(node_feat, in_W, in_b, H, ROWS, DN, DM, 0);

    for (int l = 0; l < NL; l++) {
        gather_kernel<<<(NNODE * 32 + 255) / 256, 256>>>(H, off, entries, G);
        float* dst = (l == NL - 1) ? out : H;
        gemm_ln_tf32<<<ROWS / 128, 256>>>(
            G, Wpre + (size_t)l * 24576, H, Ct + (size_t)l * NNODE * DM,
            ln_g + (size_t)l * DM, ln_b + (size_t)l * DM, dst);
    }
}